// round 2
// baseline (speedup 1.0000x reference)
#include <cuda_runtime.h>

#define NN 100000
#define EE 3200000
#define GG 512
#define HH 64
#define BN_EPS 1e-5f

// ---------------- scratch (static __device__ — no allocation) ----------------
__device__ __align__(16) float g_x4[NN * 4];     // padded input features [N][4]
__device__ __align__(16) float g_xb[NN * 64];    // current layer features [N][64]
__device__ __align__(16) float g_agg[NN * 64];   // aggregation buffer (layer0 uses [N][4] prefix)
__device__ __align__(16) float g_h[NN * 64];     // pre-BN MLP output
__device__ __align__(16) float g_w1p[4 * 64];    // W1 of layer 0 padded 3->4 rows
__device__ float g_stats[128];                   // [0:64) sum, [64:128) sumsq
__device__ __align__(16) float g_pool[GG * 64];  // graph feature sums
__device__ float g_cnt[GG];                      // graph node counts

// vector RED (sm_90+): global float4 add, no return
__device__ __forceinline__ void red_add_v4(float* p, float4 v) {
    asm volatile("red.global.add.v4.f32 [%0], {%1,%2,%3,%4};"
                 :: "l"(p), "f"(v.x), "f"(v.y), "f"(v.z), "f"(v.w) : "memory");
}

// ---------------- small utility kernels ----------------
__global__ void k_prep(const float* __restrict__ x) {
    int n = blockIdx.x * blockDim.x + threadIdx.x;
    if (n < NN) {
        float4 v;
        v.x = x[n * 3 + 0];
        v.y = x[n * 3 + 1];
        v.z = x[n * 3 + 2];
        v.w = 0.f;
        reinterpret_cast<float4*>(g_x4)[n] = v;
    }
}

__global__ void k_w1pad(const float* __restrict__ w1_0) {
    int i = threadIdx.x;  // 256 = 4*64
    int k = i >> 6, f = i & 63;
    g_w1p[i] = (k < 3) ? w1_0[k * 64 + f] : 0.f;
}

__global__ void k_zero_agg(int n4) {  // zero n4 float4s of g_agg
    int i = blockIdx.x * blockDim.x + threadIdx.x;
    if (i < n4) reinterpret_cast<float4*>(g_agg)[i] = make_float4(0.f, 0.f, 0.f, 0.f);
}

__global__ void k_zero_stats() { g_stats[threadIdx.x] = 0.f; }

__global__ void k_zero_pool() {
    int i = blockIdx.x * blockDim.x + threadIdx.x;
    if (i < GG * 64) g_pool[i] = 0.f;
    if (i < GG) g_cnt[i] = 0.f;
}

__global__ void k_cnt(const int* __restrict__ batch) {
    int n = blockIdx.x * blockDim.x + threadIdx.x;
    if (n < NN) atomicAdd(&g_cnt[batch[n]], 1.0f);
}

// ---------------- edge scatter kernels ----------------
// layer 0: thread per edge, 4-float rows
__global__ void k_edge0(const int* __restrict__ ei) {
    int e = blockIdx.x * blockDim.x + threadIdx.x;
    if (e < EE) {
        int s = ei[e];
        int d = ei[EE + e];
        float4 v = reinterpret_cast<const float4*>(g_x4)[s];
        red_add_v4(&g_agg[d * 4], v);
    }
}

// layers 1..2: 16 lanes per edge (one float4 chunk each) — fully coalesced 256B row
__global__ void k_edge64(const int* __restrict__ ei) {
    int idx = blockIdx.x * blockDim.x + threadIdx.x;
    if (idx < EE * 16) {
        int e = idx >> 4;
        int c = idx & 15;
        int s = ei[e];
        int d = ei[EE + e];
        float4 v = *reinterpret_cast<const float4*>(&g_xb[s * 64 + c * 4]);
        red_add_v4(&g_agg[d * 64 + c * 4], v);
    }
}

// ---------------- fused MLP (two matmuls + ReLU) + BN-stat partial reduce ----------------
// Tile: 64 nodes x 64 feats per block, 256 threads, 4x4 micro-tile per thread.
template <int KIN>
__global__ __launch_bounds__(256) void k_mlp(const float* __restrict__ W1,
                                             const float* __restrict__ b1,
                                             const float* __restrict__ W2,
                                             const float* __restrict__ b2) {
    __shared__ float sA[64][65];  // a / t tile, transposed [k][m]
    __shared__ float sW[64][64];  // weight tile [k][f]

    const float* __restrict__ xin = (KIN == 4) ? g_x4 : g_xb;
    const float* __restrict__ W1p = (KIN == 4) ? g_w1p : W1;

    const int m0 = blockIdx.x * 64;
    const int tid = threadIdx.x;
    const int tx = tid & 15;   // feature group (4 feats)
    const int ty = tid >> 4;   // node group (4 nodes)

    // load A = x + agg (transposed into sA)
    for (int e = tid; e < 64 * (KIN / 4); e += 256) {
        int m = e / (KIN / 4);
        int k0 = (e % (KIN / 4)) * 4;
        int n = m0 + m;
        float4 v = make_float4(0.f, 0.f, 0.f, 0.f);
        if (n < NN) {
            float4 a = *reinterpret_cast<const float4*>(&xin[n * KIN + k0]);
            float4 g = *reinterpret_cast<const float4*>(&g_agg[n * KIN + k0]);
            v = make_float4(a.x + g.x, a.y + g.y, a.z + g.z, a.w + g.w);
        }
        sA[k0 + 0][m] = v.x;
        sA[k0 + 1][m] = v.y;
        sA[k0 + 2][m] = v.z;
        sA[k0 + 3][m] = v.w;
    }
    // load W1
    for (int e = tid; e < KIN * 16; e += 256) {
        int k = e >> 4, f0 = (e & 15) * 4;
        *reinterpret_cast<float4*>(&sW[k][f0]) =
            *reinterpret_cast<const float4*>(&W1p[k * 64 + f0]);
    }
    __syncthreads();

    // stage 1: acc = A @ W1
    float acc[4][4] = {};
    #pragma unroll
    for (int k = 0; k < KIN; k++) {
        float a0 = sA[k][ty * 4 + 0];
        float a1 = sA[k][ty * 4 + 1];
        float a2 = sA[k][ty * 4 + 2];
        float a3 = sA[k][ty * 4 + 3];
        float4 w = *reinterpret_cast<float4*>(&sW[k][tx * 4]);
        acc[0][0] += a0 * w.x; acc[0][1] += a0 * w.y; acc[0][2] += a0 * w.z; acc[0][3] += a0 * w.w;
        acc[1][0] += a1 * w.x; acc[1][1] += a1 * w.y; acc[1][2] += a1 * w.z; acc[1][3] += a1 * w.w;
        acc[2][0] += a2 * w.x; acc[2][1] += a2 * w.y; acc[2][2] += a2 * w.z; acc[2][3] += a2 * w.w;
        acc[3][0] += a3 * w.x; acc[3][1] += a3 * w.y; acc[3][2] += a3 * w.z; acc[3][3] += a3 * w.w;
    }
    float4 b1v = *reinterpret_cast<const float4*>(&b1[tx * 4]);
    float t[4][4];
    #pragma unroll
    for (int i = 0; i < 4; i++) {
        t[i][0] = fmaxf(acc[i][0] + b1v.x, 0.f);
        t[i][1] = fmaxf(acc[i][1] + b1v.y, 0.f);
        t[i][2] = fmaxf(acc[i][2] + b1v.z, 0.f);
        t[i][3] = fmaxf(acc[i][3] + b1v.w, 0.f);
    }
    __syncthreads();  // everyone done reading sA/sW for stage 1

    // write T (transposed) into sA, load W2
    #pragma unroll
    for (int i = 0; i < 4; i++)
        #pragma unroll
        for (int j = 0; j < 4; j++)
            sA[tx * 4 + j][ty * 4 + i] = t[i][j];
    for (int e = tid; e < 1024; e += 256) {
        int k = e >> 4, f0 = (e & 15) * 4;
        *reinterpret_cast<float4*>(&sW[k][f0]) =
            *reinterpret_cast<const float4*>(&W2[k * 64 + f0]);
    }
    __syncthreads();

    // stage 2: acc = T @ W2
    #pragma unroll
    for (int i = 0; i < 4; i++)
        #pragma unroll
        for (int j = 0; j < 4; j++) acc[i][j] = 0.f;
    #pragma unroll 8
    for (int k = 0; k < 64; k++) {
        float a0 = sA[k][ty * 4 + 0];
        float a1 = sA[k][ty * 4 + 1];
        float a2 = sA[k][ty * 4 + 2];
        float a3 = sA[k][ty * 4 + 3];
        float4 w = *reinterpret_cast<float4*>(&sW[k][tx * 4]);
        acc[0][0] += a0 * w.x; acc[0][1] += a0 * w.y; acc[0][2] += a0 * w.z; acc[0][3] += a0 * w.w;
        acc[1][0] += a1 * w.x; acc[1][1] += a1 * w.y; acc[1][2] += a1 * w.z; acc[1][3] += a1 * w.w;
        acc[2][0] += a2 * w.x; acc[2][1] += a2 * w.y; acc[2][2] += a2 * w.z; acc[2][3] += a2 * w.w;
        acc[3][0] += a3 * w.x; acc[3][1] += a3 * w.y; acc[3][2] += a3 * w.z; acc[3][3] += a3 * w.w;
    }
    float4 b2v = *reinterpret_cast<const float4*>(&b2[tx * 4]);

    // h store + BN stat partials
    float s[4] = {0.f, 0.f, 0.f, 0.f};
    float ss[4] = {0.f, 0.f, 0.f, 0.f};
    #pragma unroll
    for (int i = 0; i < 4; i++) {
        int n = m0 + ty * 4 + i;
        float4 hv = make_float4(acc[i][0] + b2v.x, acc[i][1] + b2v.y,
                                acc[i][2] + b2v.z, acc[i][3] + b2v.w);
        if (n < NN) {
            *reinterpret_cast<float4*>(&g_h[n * 64 + tx * 4]) = hv;
            s[0] += hv.x; ss[0] += hv.x * hv.x;
            s[1] += hv.y; ss[1] += hv.y * hv.y;
            s[2] += hv.z; ss[2] += hv.z * hv.z;
            s[3] += hv.w; ss[3] += hv.w * hv.w;
        }
    }
    __syncthreads();  // done reading sA/sW for stage 2

    // block-level BN stat reduce: sA holds sums, sW holds sumsqs ([feat][ty])
    #pragma unroll
    for (int j = 0; j < 4; j++) {
        sA[tx * 4 + j][ty] = s[j];
        sW[tx * 4 + j][ty] = ss[j];
    }
    __syncthreads();
    if (tid < 64) {
        float a = 0.f, b = 0.f;
        #pragma unroll
        for (int i = 0; i < 16; i++) {
            a += sA[tid][i];
            b += sW[tid][i];
        }
        atomicAdd(&g_stats[tid], a);
        atomicAdd(&g_stats[64 + tid], b);
    }
}

// ---------------- BN apply + ReLU (optionally fused graph-pool scatter) ----------------
template <bool POOL>
__global__ void k_bn(const float* __restrict__ gamma, const float* __restrict__ beta,
                     const int* __restrict__ batch) {
    int idx = blockIdx.x * blockDim.x + threadIdx.x;
    if (idx >= NN * 16) return;
    int n = idx >> 4;
    int f0 = (idx & 15) * 4;
    const float inv = 1.0f / (float)NN;

    float4 hv = *reinterpret_cast<const float4*>(&g_h[n * 64 + f0]);
    float4 o;
    {
        float mu = g_stats[f0 + 0] * inv;
        float var = g_stats[64 + f0 + 0] * inv - mu * mu;
        o.x = fmaxf((hv.x - mu) * rsqrtf(var + BN_EPS) * gamma[f0 + 0] + beta[f0 + 0], 0.f);
    }
    {
        float mu = g_stats[f0 + 1] * inv;
        float var = g_stats[64 + f0 + 1] * inv - mu * mu;
        o.y = fmaxf((hv.y - mu) * rsqrtf(var + BN_EPS) * gamma[f0 + 1] + beta[f0 + 1], 0.f);
    }
    {
        float mu = g_stats[f0 + 2] * inv;
        float var = g_stats[64 + f0 + 2] * inv - mu * mu;
        o.z = fmaxf((hv.z - mu) * rsqrtf(var + BN_EPS) * gamma[f0 + 2] + beta[f0 + 2], 0.f);
    }
    {
        float mu = g_stats[f0 + 3] * inv;
        float var = g_stats[64 + f0 + 3] * inv - mu * mu;
        o.w = fmaxf((hv.w - mu) * rsqrtf(var + BN_EPS) * gamma[f0 + 3] + beta[f0 + 3], 0.f);
    }
    *reinterpret_cast<float4*>(&g_xb[n * 64 + f0]) = o;
    if (POOL) {
        int g = batch[n];
        red_add_v4(&g_pool[g * 64 + f0], o);
    }
}

// ---------------- final projection ----------------
__global__ void k_out(const float* __restrict__ wout, const float* __restrict__ bout,
                      float* __restrict__ out) {
    __shared__ float mean[64];
    int g = blockIdx.x, f = threadIdx.x;
    float c = g_cnt[g];
    float sum = g_pool[g * 64 + f];
    mean[f] = (c > 0.f) ? sum / fmaxf(c, 1.f) : 0.f;
    __syncthreads();
    float acc = bout[f];
    #pragma unroll 8
    for (int k = 0; k < 64; k++) acc += mean[k] * wout[k * 64 + f];
    out[g * 64 + f] = acc;
}

// ---------------- launcher ----------------
extern "C" void kernel_launch(void* const* d_in, const int* in_sizes, int n_in,
                              void* d_out, int out_size) {
    const float* x     = (const float*)d_in[0];
    const int*   ei    = (const int*)d_in[1];
    const int*   batch = (const int*)d_in[2];
    const float* w1_0  = (const float*)d_in[3];
    const float* w1_r  = (const float*)d_in[4];
    const float* b1    = (const float*)d_in[5];
    const float* w2    = (const float*)d_in[6];
    const float* b2    = (const float*)d_in[7];
    const float* gamma = (const float*)d_in[8];
    const float* beta  = (const float*)d_in[9];
    const float* wout  = (const float*)d_in[10];
    const float* bout  = (const float*)d_in[11];
    float* out = (float*)d_out;

    const int TPB = 256;
    const int nodeBlocks = (NN + TPB - 1) / TPB;           // 391
    const int mlpBlocks  = (NN + 63) / 64;                 // 1563
    const int bnBlocks   = (NN * 16 + TPB - 1) / TPB;      // 6250
    const int e0Blocks   = (EE + TPB - 1) / TPB;           // 12500
    const int e64Blocks  = (EE * 16 + TPB - 1) / TPB;      // 200000

    k_prep<<<nodeBlocks, TPB>>>(x);
    k_w1pad<<<1, 256>>>(w1_0);

    // ---- layer 0 (KIN = 4, padded) ----
    k_zero_agg<<<(NN + TPB - 1) / TPB, TPB>>>(NN);         // N float4s = [N][4]
    k_zero_stats<<<1, 128>>>();
    k_edge0<<<e0Blocks, TPB>>>(ei);
    k_mlp<4><<<mlpBlocks, TPB>>>(nullptr, b1 + 0, w2 + 0, b2 + 0);
    k_bn<false><<<bnBlocks, TPB>>>(gamma + 0, beta + 0, nullptr);

    // ---- layer 1 ----
    k_zero_agg<<<(NN * 16 + TPB - 1) / TPB, TPB>>>(NN * 16);
    k_zero_stats<<<1, 128>>>();
    k_edge64<<<e64Blocks, TPB>>>(ei);
    k_mlp<64><<<mlpBlocks, TPB>>>(w1_r, b1 + 64, w2 + 4096, b2 + 64);
    k_bn<false><<<bnBlocks, TPB>>>(gamma + 64, beta + 64, nullptr);

    // ---- layer 2 (fuse pool into BN apply) ----
    k_zero_agg<<<(NN * 16 + TPB - 1) / TPB, TPB>>>(NN * 16);
    k_zero_stats<<<1, 128>>>();
    k_zero_pool<<<(GG * 64 + TPB - 1) / TPB, TPB>>>();
    k_edge64<<<e64Blocks, TPB>>>(ei);
    k_mlp<64><<<mlpBlocks, TPB>>>(w1_r + 4096, b1 + 128, w2 + 8192, b2 + 128);
    k_cnt<<<nodeBlocks, TPB>>>(batch);
    k_bn<true><<<bnBlocks, TPB>>>(gamma + 128, beta + 128, batch);

    // ---- output projection ----
    k_out<<<GG, 64>>>(wout, bout, out);
}

// round 3
// speedup vs baseline: 2.1468x; 2.1468x over previous
#include <cuda_runtime.h>

#define NN 100000
#define EE 3200000
#define GG 512
#define HH 64
#define BN_EPS 1e-5f
#define SCAN_BLK 1024
#define NSB ((NN + SCAN_BLK - 1) / SCAN_BLK)   // 98

typedef unsigned long long u64;

// ---------------- scratch (static __device__ — no allocation) ----------------
__device__ __align__(16) float g_x4[NN * 4];     // padded input features [N][4]
__device__ __align__(16) float g_xb[NN * 64];    // current layer features [N][64]
__device__ __align__(16) float g_agg[NN * 64];   // (1+eps)*x + sum_neighbors (MLP input)
__device__ __align__(16) float g_h[NN * 64];     // pre-BN MLP output
__device__ __align__(16) float g_w1p[4 * 64];    // W1 of layer 0 padded 3->4 rows
__device__ float g_stats[128];                   // [0:64) sum, [64:128) sumsq
__device__ __align__(16) float g_pool[GG * 64];  // graph feature sums
__device__ float g_cnt[GG];                      // graph node counts
// CSR
__device__ int g_deg[NN];
__device__ int g_off[NN];
__device__ int g_cur[NN];
__device__ int g_srcs[EE];
__device__ int g_bsum[NSB];

// vector RED (sm_90+): global float4 add, no return
__device__ __forceinline__ void red_add_v4(float* p, float4 v) {
    asm volatile("red.global.add.v4.f32 [%0], {%1,%2,%3,%4};"
                 :: "l"(p), "f"(v.x), "f"(v.y), "f"(v.z), "f"(v.w) : "memory");
}

// packed f32x2 helpers (Blackwell FFMA2 — ptxas never auto-generates this)
__device__ __forceinline__ u64 pk2(float lo, float hi) {
    u64 r; asm("mov.b64 %0, {%1,%2};" : "=l"(r) : "f"(lo), "f"(hi)); return r;
}
__device__ __forceinline__ u64 fma2(u64 a, u64 b, u64 c) {
    u64 d; asm("fma.rn.f32x2 %0, %1, %2, %3;" : "=l"(d) : "l"(a), "l"(b), "l"(c)); return d;
}
__device__ __forceinline__ float2 upk(u64 v) {
    float2 f; asm("mov.b64 {%0,%1}, %2;" : "=f"(f.x), "=f"(f.y) : "l"(v)); return f;
}

// ---------------- prep ----------------
__global__ void k_prep(const float* __restrict__ x, const int* __restrict__ batch) {
    int n = blockIdx.x * blockDim.x + threadIdx.x;
    if (n < NN) {
        float4 v;
        v.x = x[n * 3 + 0];
        v.y = x[n * 3 + 1];
        v.z = x[n * 3 + 2];
        v.w = 0.f;
        reinterpret_cast<float4*>(g_x4)[n] = v;
        atomicAdd(&g_cnt[batch[n]], 1.0f);   // sorted batch -> REDUX-aggregated
    }
}

__global__ void k_w1pad(const float* __restrict__ w1_0) {
    int i = threadIdx.x;  // 256 = 4*64
    int k = i >> 6, f = i & 63;
    g_w1p[i] = (k < 3) ? w1_0[k * 64 + f] : 0.f;
}

__global__ void k_zero_stats() { g_stats[threadIdx.x] = 0.f; }

__global__ void k_zero_pool() {
    int i = blockIdx.x * blockDim.x + threadIdx.x;
    if (i < GG * 64) g_pool[i] = 0.f;
    if (i < GG) g_cnt[i] = 0.f;
}

__global__ void k_zero_deg() {
    int i = blockIdx.x * blockDim.x + threadIdx.x;
    if (i < NN) g_deg[i] = 0;
}

// ---------------- CSR build ----------------
__global__ void k_hist(const int* __restrict__ ei) {
    int e = blockIdx.x * blockDim.x + threadIdx.x;
    if (e < EE) atomicAdd(&g_deg[ei[EE + e]], 1);
}

__global__ void k_scan_sum() {  // NSB blocks x 256 threads; 4 elems/thread
    __shared__ int sh[256];
    int b = blockIdx.x, t = threadIdx.x;
    int base = b * SCAN_BLK + t * 4;
    int s = 0;
    #pragma unroll
    for (int i = 0; i < 4; i++) {
        int idx = base + i;
        if (idx < NN) s += g_deg[idx];
    }
    sh[t] = s;
    __syncthreads();
    for (int d = 128; d > 0; d >>= 1) {
        if (t < d) sh[t] += sh[t + d];
        __syncthreads();
    }
    if (t == 0) g_bsum[b] = sh[0];
}

__global__ void k_scan_top() {  // serial exclusive scan over 98 partials
    if (threadIdx.x == 0) {
        int run = 0;
        for (int i = 0; i < NSB; i++) { int v = g_bsum[i]; g_bsum[i] = run; run += v; }
    }
}

__global__ void k_scan_out() {  // NSB blocks x 256 threads
    __shared__ int sh[256];
    int b = blockIdx.x, t = threadIdx.x;
    int base = b * SCAN_BLK + t * 4;
    int loc[4];
    int s = 0;
    #pragma unroll
    for (int i = 0; i < 4; i++) {
        int idx = base + i;
        int v = (idx < NN) ? g_deg[idx] : 0;
        loc[i] = s; s += v;
    }
    sh[t] = s;
    __syncthreads();
    for (int d = 1; d < 256; d <<= 1) {
        int v = (t >= d) ? sh[t - d] : 0;
        __syncthreads();
        sh[t] += v;
        __syncthreads();
    }
    int excl = sh[t] - s + g_bsum[b];
    #pragma unroll
    for (int i = 0; i < 4; i++) {
        int idx = base + i;
        if (idx < NN) {
            int o = excl + loc[i];
            g_off[idx] = o;
            g_cur[idx] = o;
        }
    }
}

__global__ void k_scatter(const int* __restrict__ ei) {
    int e = blockIdx.x * blockDim.x + threadIdx.x;
    if (e < EE) {
        int s = ei[e];
        int d = ei[EE + e];
        int p = atomicAdd(&g_cur[d], 1);
        g_srcs[p] = s;
    }
}

// ---------------- gather aggregation (CSR, no atomics) ----------------
// layer 0: warp per node, 4 feats; lane = c(0..3) + 4*sub(0..7)
__global__ void k_gather4() {
    int w = (blockIdx.x * blockDim.x + threadIdx.x) >> 5;
    if (w >= NN) return;
    int lane = threadIdx.x & 31;
    int c = lane & 3, sub = lane >> 2;
    int beg = g_off[w], dg = g_deg[w];
    float acc = (sub == 0) ? g_x4[w * 4 + c] : 0.f;
    for (int j = beg + sub; j < beg + dg; j += 8) {
        int s = g_srcs[j];
        acc += g_x4[s * 4 + c];
    }
    acc += __shfl_down_sync(0xffffffffu, acc, 16);
    acc += __shfl_down_sync(0xffffffffu, acc, 8);
    acc += __shfl_down_sync(0xffffffffu, acc, 4);
    if (sub == 0) g_agg[w * 4 + c] = acc;
}

// layers 1..2: warp per node, 64 feats; lane = c(0..15) + 16*half
__global__ void k_gather64() {
    int w = (blockIdx.x * blockDim.x + threadIdx.x) >> 5;
    if (w >= NN) return;
    int lane = threadIdx.x & 31;
    int c = lane & 15, half = lane >> 4;
    int beg = g_off[w], dg = g_deg[w];
    float4 acc;
    if (half == 0) acc = *reinterpret_cast<const float4*>(&g_xb[w * 64 + c * 4]);
    else acc = make_float4(0.f, 0.f, 0.f, 0.f);
    for (int j = beg + half; j < beg + dg; j += 2) {
        int s = g_srcs[j];
        float4 v = *reinterpret_cast<const float4*>(&g_xb[s * 64 + c * 4]);
        acc.x += v.x; acc.y += v.y; acc.z += v.z; acc.w += v.w;
    }
    acc.x += __shfl_down_sync(0xffffffffu, acc.x, 16);
    acc.y += __shfl_down_sync(0xffffffffu, acc.y, 16);
    acc.z += __shfl_down_sync(0xffffffffu, acc.z, 16);
    acc.w += __shfl_down_sync(0xffffffffu, acc.w, 16);
    if (half == 0) *reinterpret_cast<float4*>(&g_agg[w * 64 + c * 4]) = acc;
}

// ---------------- fused MLP (two matmuls + ReLU) + BN-stat partial reduce ----------------
// Tile: 64 nodes x 64 feats per block, 256 threads, 4x4 micro-tile (f32x2 over node pairs)
template <int KIN>
__global__ __launch_bounds__(256) void k_mlp(const float* __restrict__ W1,
                                             const float* __restrict__ b1,
                                             const float* __restrict__ W2,
                                             const float* __restrict__ b2) {
    __shared__ float sA[64][68];  // [k][m], padded to keep float4 alignment
    __shared__ float sW[64][64];  // [k][f]

    const float* __restrict__ W1p = (KIN == 4) ? g_w1p : W1;

    const int m0 = blockIdx.x * 64;
    const int tid = threadIdx.x;
    const int tx = tid & 15;   // feature group (4 feats)
    const int ty = tid >> 4;   // node group (4 nodes)

    // load A = agg (already includes self term), transposed into sA
    for (int e = tid; e < 64 * (KIN / 4); e += 256) {
        int m = e / (KIN / 4);
        int k0 = (e % (KIN / 4)) * 4;
        int n = m0 + m;
        float4 v = make_float4(0.f, 0.f, 0.f, 0.f);
        if (n < NN) v = *reinterpret_cast<const float4*>(&g_agg[n * KIN + k0]);
        sA[k0 + 0][m] = v.x;
        sA[k0 + 1][m] = v.y;
        sA[k0 + 2][m] = v.z;
        sA[k0 + 3][m] = v.w;
    }
    // load W1
    for (int e = tid; e < KIN * 16; e += 256) {
        int k = e >> 4, f0 = (e & 15) * 4;
        *reinterpret_cast<float4*>(&sW[k][f0]) =
            *reinterpret_cast<const float4*>(&W1p[k * 64 + f0]);
    }
    __syncthreads();

    // stage 1: acc = A @ W1    acc[f][p] : feature tx*4+f, node pair (ty*4+2p, ty*4+2p+1)
    u64 acc[4][2] = {{0ull, 0ull}, {0ull, 0ull}, {0ull, 0ull}, {0ull, 0ull}};
    #pragma unroll
    for (int k = 0; k < KIN; k++) {
        float4 av = *reinterpret_cast<float4*>(&sA[k][ty * 4]);
        u64 a01 = pk2(av.x, av.y), a23 = pk2(av.z, av.w);
        float4 wv = *reinterpret_cast<float4*>(&sW[k][tx * 4]);
        u64 w0 = pk2(wv.x, wv.x), w1 = pk2(wv.y, wv.y);
        u64 w2_ = pk2(wv.z, wv.z), w3 = pk2(wv.w, wv.w);
        acc[0][0] = fma2(a01, w0, acc[0][0]); acc[0][1] = fma2(a23, w0, acc[0][1]);
        acc[1][0] = fma2(a01, w1, acc[1][0]); acc[1][1] = fma2(a23, w1, acc[1][1]);
        acc[2][0] = fma2(a01, w2_, acc[2][0]); acc[2][1] = fma2(a23, w2_, acc[2][1]);
        acc[3][0] = fma2(a01, w3, acc[3][0]); acc[3][1] = fma2(a23, w3, acc[3][1]);
    }
    float4 b1v = *reinterpret_cast<const float4*>(&b1[tx * 4]);
    __syncthreads();  // stage-1 readers done before sA/sW overwrite

    // bias + ReLU, write transposed back into sA: sA[feat][node]
    {
        float bb[4] = {b1v.x, b1v.y, b1v.z, b1v.w};
        #pragma unroll
        for (int f = 0; f < 4; f++) {
            float2 v0 = upk(acc[f][0]);
            float2 v1 = upk(acc[f][1]);
            sA[tx * 4 + f][ty * 4 + 0] = fmaxf(v0.x + bb[f], 0.f);
            sA[tx * 4 + f][ty * 4 + 1] = fmaxf(v0.y + bb[f], 0.f);
            sA[tx * 4 + f][ty * 4 + 2] = fmaxf(v1.x + bb[f], 0.f);
            sA[tx * 4 + f][ty * 4 + 3] = fmaxf(v1.y + bb[f], 0.f);
        }
    }
    for (int e = tid; e < 1024; e += 256) {
        int k = e >> 4, f0 = (e & 15) * 4;
        *reinterpret_cast<float4*>(&sW[k][f0]) =
            *reinterpret_cast<const float4*>(&W2[k * 64 + f0]);
    }
    __syncthreads();

    // stage 2: acc = T @ W2
    #pragma unroll
    for (int f = 0; f < 4; f++) { acc[f][0] = 0ull; acc[f][1] = 0ull; }
    #pragma unroll 8
    for (int k = 0; k < 64; k++) {
        float4 av = *reinterpret_cast<float4*>(&sA[k][ty * 4]);
        u64 a01 = pk2(av.x, av.y), a23 = pk2(av.z, av.w);
        float4 wv = *reinterpret_cast<float4*>(&sW[k][tx * 4]);
        u64 w0 = pk2(wv.x, wv.x), w1 = pk2(wv.y, wv.y);
        u64 w2_ = pk2(wv.z, wv.z), w3 = pk2(wv.w, wv.w);
        acc[0][0] = fma2(a01, w0, acc[0][0]); acc[0][1] = fma2(a23, w0, acc[0][1]);
        acc[1][0] = fma2(a01, w1, acc[1][0]); acc[1][1] = fma2(a23, w1, acc[1][1]);
        acc[2][0] = fma2(a01, w2_, acc[2][0]); acc[2][1] = fma2(a23, w2_, acc[2][1]);
        acc[3][0] = fma2(a01, w3, acc[3][0]); acc[3][1] = fma2(a23, w3, acc[3][1]);
    }
    float4 b2v = *reinterpret_cast<const float4*>(&b2[tx * 4]);

    // unpack -> per-node float4 over this thread's 4 features
    float2 u0a = upk(acc[0][0]), u0b = upk(acc[0][1]);
    float2 u1a = upk(acc[1][0]), u1b = upk(acc[1][1]);
    float2 u2a = upk(acc[2][0]), u2b = upk(acc[2][1]);
    float2 u3a = upk(acc[3][0]), u3b = upk(acc[3][1]);
    float4 hv[4];
    hv[0] = make_float4(u0a.x + b2v.x, u1a.x + b2v.y, u2a.x + b2v.z, u3a.x + b2v.w);
    hv[1] = make_float4(u0a.y + b2v.x, u1a.y + b2v.y, u2a.y + b2v.z, u3a.y + b2v.w);
    hv[2] = make_float4(u0b.x + b2v.x, u1b.x + b2v.y, u2b.x + b2v.z, u3b.x + b2v.w);
    hv[3] = make_float4(u0b.y + b2v.x, u1b.y + b2v.y, u2b.y + b2v.z, u3b.y + b2v.w);

    // h store + BN stat partials (per-feature sums over this thread's 4 nodes)
    float s[4] = {0.f, 0.f, 0.f, 0.f};
    float ss[4] = {0.f, 0.f, 0.f, 0.f};
    #pragma unroll
    for (int i = 0; i < 4; i++) {
        int n = m0 + ty * 4 + i;
        if (n < NN) {
            *reinterpret_cast<float4*>(&g_h[n * 64 + tx * 4]) = hv[i];
            s[0] += hv[i].x; ss[0] += hv[i].x * hv[i].x;
            s[1] += hv[i].y; ss[1] += hv[i].y * hv[i].y;
            s[2] += hv[i].z; ss[2] += hv[i].z * hv[i].z;
            s[3] += hv[i].w; ss[3] += hv[i].w * hv[i].w;
        }
    }
    __syncthreads();  // stage-2 readers done before reuse as scratch

    // block-level BN stat reduce: sA holds sums, sW holds sumsqs ([feat][ty])
    #pragma unroll
    for (int j = 0; j < 4; j++) {
        sA[tx * 4 + j][ty] = s[j];
        sW[tx * 4 + j][ty] = ss[j];
    }
    __syncthreads();
    if (tid < 64) {
        float a = 0.f, b = 0.f;
        #pragma unroll
        for (int i = 0; i < 16; i++) {
            a += sA[tid][i];
            b += sW[tid][i];
        }
        atomicAdd(&g_stats[tid], a);
        atomicAdd(&g_stats[64 + tid], b);
    }
}

// ---------------- BN apply + ReLU (optionally fused graph-pool scatter) ----------------
template <bool POOL>
__global__ void k_bn(const float* __restrict__ gamma, const float* __restrict__ beta,
                     const int* __restrict__ batch) {
    int idx = blockIdx.x * blockDim.x + threadIdx.x;
    if (idx >= NN * 16) return;
    int n = idx >> 4;
    int f0 = (idx & 15) * 4;
    const float inv = 1.0f / (float)NN;

    float4 hv = *reinterpret_cast<const float4*>(&g_h[n * 64 + f0]);
    float4 o;
    {
        float mu = g_stats[f0 + 0] * inv;
        float var = g_stats[64 + f0 + 0] * inv - mu * mu;
        o.x = fmaxf((hv.x - mu) * rsqrtf(var + BN_EPS) * gamma[f0 + 0] + beta[f0 + 0], 0.f);
    }
    {
        float mu = g_stats[f0 + 1] * inv;
        float var = g_stats[64 + f0 + 1] * inv - mu * mu;
        o.y = fmaxf((hv.y - mu) * rsqrtf(var + BN_EPS) * gamma[f0 + 1] + beta[f0 + 1], 0.f);
    }
    {
        float mu = g_stats[f0 + 2] * inv;
        float var = g_stats[64 + f0 + 2] * inv - mu * mu;
        o.z = fmaxf((hv.z - mu) * rsqrtf(var + BN_EPS) * gamma[f0 + 2] + beta[f0 + 2], 0.f);
    }
    {
        float mu = g_stats[f0 + 3] * inv;
        float var = g_stats[64 + f0 + 3] * inv - mu * mu;
        o.w = fmaxf((hv.w - mu) * rsqrtf(var + BN_EPS) * gamma[f0 + 3] + beta[f0 + 3], 0.f);
    }
    *reinterpret_cast<float4*>(&g_xb[n * 64 + f0]) = o;
    if (POOL) {
        int g = batch[n];
        red_add_v4(&g_pool[g * 64 + f0], o);
    }
}

// ---------------- final projection ----------------
__global__ void k_out(const float* __restrict__ wout, const float* __restrict__ bout,
                      float* __restrict__ out) {
    __shared__ float mean[64];
    int g = blockIdx.x, f = threadIdx.x;
    float c = g_cnt[g];
    float sum = g_pool[g * 64 + f];
    mean[f] = (c > 0.f) ? sum / fmaxf(c, 1.f) : 0.f;
    __syncthreads();
    float acc = bout[f];
    #pragma unroll 8
    for (int k = 0; k < 64; k++) acc += mean[k] * wout[k * 64 + f];
    out[g * 64 + f] = acc;
}

// ---------------- launcher ----------------
extern "C" void kernel_launch(void* const* d_in, const int* in_sizes, int n_in,
                              void* d_out, int out_size) {
    const float* x     = (const float*)d_in[0];
    const int*   ei    = (const int*)d_in[1];
    const int*   batch = (const int*)d_in[2];
    const float* w1_0  = (const float*)d_in[3];
    const float* w1_r  = (const float*)d_in[4];
    const float* b1    = (const float*)d_in[5];
    const float* w2    = (const float*)d_in[6];
    const float* b2    = (const float*)d_in[7];
    const float* gamma = (const float*)d_in[8];
    const float* beta  = (const float*)d_in[9];
    const float* wout  = (const float*)d_in[10];
    const float* bout  = (const float*)d_in[11];
    float* out = (float*)d_out;

    const int TPB = 256;
    const int nodeBlocks  = (NN + TPB - 1) / TPB;        // 391
    const int mlpBlocks   = (NN + 63) / 64;              // 1563
    const int bnBlocks    = (NN * 16 + TPB - 1) / TPB;   // 6250
    const int edgeBlocks  = (EE + TPB - 1) / TPB;        // 12500
    const int warpBlocks  = (NN * 32 + TPB - 1) / TPB;   // 12500 (warp per node)

    // prep + CSR build
    k_zero_pool<<<(GG * 64 + TPB - 1) / TPB, TPB>>>();
    k_prep<<<nodeBlocks, TPB>>>(x, batch);
    k_w1pad<<<1, 256>>>(w1_0);
    k_zero_deg<<<nodeBlocks, TPB>>>();
    k_hist<<<edgeBlocks, TPB>>>(ei);
    k_scan_sum<<<NSB, 256>>>();
    k_scan_top<<<1, 32>>>();
    k_scan_out<<<NSB, 256>>>();
    k_scatter<<<edgeBlocks, TPB>>>(ei);

    // ---- layer 0 (KIN = 4, padded) ----
    k_zero_stats<<<1, 128>>>();
    k_gather4<<<warpBlocks, TPB>>>();
    k_mlp<4><<<mlpBlocks, TPB>>>(nullptr, b1 + 0, w2 + 0, b2 + 0);
    k_bn<false><<<bnBlocks, TPB>>>(gamma + 0, beta + 0, nullptr);

    // ---- layer 1 ----
    k_zero_stats<<<1, 128>>>();
    k_gather64<<<warpBlocks, TPB>>>();
    k_mlp<64><<<mlpBlocks, TPB>>>(w1_r, b1 + 64, w2 + 4096, b2 + 64);
    k_bn<false><<<bnBlocks, TPB>>>(gamma + 64, beta + 64, nullptr);

    // ---- layer 2 (fuse pool into BN apply) ----
    k_zero_stats<<<1, 128>>>();
    k_gather64<<<warpBlocks, TPB>>>();
    k_mlp<64><<<mlpBlocks, TPB>>>(w1_r + 4096, b1 + 128, w2 + 8192, b2 + 128);
    k_bn<true><<<bnBlocks, TPB>>>(gamma + 128, beta + 128, batch);

    // ---- output projection ----
    k_out<<<GG, 64>>>(wout, bout, out);
}

// round 4
// speedup vs baseline: 2.2404x; 1.0436x over previous
#include <cuda_runtime.h>
#include <cuda_fp16.h>

#define NN 100000
#define EE 3200000
#define GG 512
#define HH 64
#define BN_EPS 1e-5f
#define SCAN_BLK 1024
#define NSB ((NN + SCAN_BLK - 1) / SCAN_BLK)   // 98

typedef unsigned long long u64;

// ---------------- scratch (static __device__ — no allocation) ----------------
__device__ __align__(16) float g_x4[NN * 4];      // padded input features [N][4]
__device__ __align__(16) __half g_xh[NN * 64];    // current activations, fp16 [N][64]
__device__ __align__(16) float g_agg[NN * 64];    // x + sum_neighbors (MLP input, fp32)
__device__ __align__(16) float g_h[NN * 64];      // pre-BN MLP output
__device__ __align__(16) float g_w1p[4 * 64];     // W1 of layer 0 padded 3->4 rows
__device__ float g_stats[128];                    // [0:64) sum, [64:128) sumsq
__device__ __align__(16) float g_pool[GG * 64];   // graph feature sums
__device__ float g_cnt[GG];                       // graph node counts
// CSR
__device__ int g_deg[NN];
__device__ int g_off[NN];
__device__ int g_cur[NN];
__device__ int g_srcs[EE];
__device__ int g_bsum[NSB];

// vector RED (sm_90+): global float4 add, no return
__device__ __forceinline__ void red_add_v4(float* p, float4 v) {
    asm volatile("red.global.add.v4.f32 [%0], {%1,%2,%3,%4};"
                 :: "l"(p), "f"(v.x), "f"(v.y), "f"(v.z), "f"(v.w) : "memory");
}

// packed f32x2 helpers (Blackwell FFMA2 — ptxas never auto-generates this)
__device__ __forceinline__ u64 pk2(float lo, float hi) {
    u64 r; asm("mov.b64 %0, {%1,%2};" : "=l"(r) : "f"(lo), "f"(hi)); return r;
}
__device__ __forceinline__ u64 fma2(u64 a, u64 b, u64 c) {
    u64 d; asm("fma.rn.f32x2 %0, %1, %2, %3;" : "=l"(d) : "l"(a), "l"(b), "l"(c)); return d;
}
__device__ __forceinline__ float2 upk(u64 v) {
    float2 f; asm("mov.b64 {%0,%1}, %2;" : "=f"(f.x), "=f"(f.y) : "l"(v)); return f;
}

// ---------------- prep ----------------
__global__ void k_prep(const float* __restrict__ x, const int* __restrict__ batch) {
    int n = blockIdx.x * blockDim.x + threadIdx.x;
    if (n < NN) {
        float4 v;
        v.x = x[n * 3 + 0];
        v.y = x[n * 3 + 1];
        v.z = x[n * 3 + 2];
        v.w = 0.f;
        reinterpret_cast<float4*>(g_x4)[n] = v;
        atomicAdd(&g_cnt[batch[n]], 1.0f);
    }
}

__global__ void k_w1pad(const float* __restrict__ w1_0) {
    int i = threadIdx.x;  // 256 = 4*64
    int k = i >> 6, f = i & 63;
    g_w1p[i] = (k < 3) ? w1_0[k * 64 + f] : 0.f;
}

__global__ void k_zero_stats() { g_stats[threadIdx.x] = 0.f; }

__global__ void k_zero_pool() {
    int i = blockIdx.x * blockDim.x + threadIdx.x;
    if (i < GG * 64) g_pool[i] = 0.f;
    if (i < GG) g_cnt[i] = 0.f;
}

__global__ void k_zero_deg() {
    int i = blockIdx.x * blockDim.x + threadIdx.x;
    if (i < NN) g_deg[i] = 0;
}

// ---------------- CSR build ----------------
__global__ void k_hist(const int* __restrict__ ei) {
    int e = blockIdx.x * blockDim.x + threadIdx.x;
    if (e < EE) atomicAdd(&g_deg[ei[EE + e]], 1);
}

__global__ void k_scan_sum() {  // NSB blocks x 256 threads; 4 elems/thread
    __shared__ int sh[256];
    int b = blockIdx.x, t = threadIdx.x;
    int base = b * SCAN_BLK + t * 4;
    int s = 0;
    #pragma unroll
    for (int i = 0; i < 4; i++) {
        int idx = base + i;
        if (idx < NN) s += g_deg[idx];
    }
    sh[t] = s;
    __syncthreads();
    for (int d = 128; d > 0; d >>= 1) {
        if (t < d) sh[t] += sh[t + d];
        __syncthreads();
    }
    if (t == 0) g_bsum[b] = sh[0];
}

__global__ void k_scan_top() {  // serial exclusive scan over 98 partials
    if (threadIdx.x == 0) {
        int run = 0;
        for (int i = 0; i < NSB; i++) { int v = g_bsum[i]; g_bsum[i] = run; run += v; }
    }
}

__global__ void k_scan_out() {  // NSB blocks x 256 threads
    __shared__ int sh[256];
    int b = blockIdx.x, t = threadIdx.x;
    int base = b * SCAN_BLK + t * 4;
    int loc[4];
    int s = 0;
    #pragma unroll
    for (int i = 0; i < 4; i++) {
        int idx = base + i;
        int v = (idx < NN) ? g_deg[idx] : 0;
        loc[i] = s; s += v;
    }
    sh[t] = s;
    __syncthreads();
    for (int d = 1; d < 256; d <<= 1) {
        int v = (t >= d) ? sh[t - d] : 0;
        __syncthreads();
        sh[t] += v;
        __syncthreads();
    }
    int excl = sh[t] - s + g_bsum[b];
    #pragma unroll
    for (int i = 0; i < 4; i++) {
        int idx = base + i;
        if (idx < NN) {
            int o = excl + loc[i];
            g_off[idx] = o;
            g_cur[idx] = o;
        }
    }
}

__global__ void k_scatter(const int* __restrict__ ei) {
    int e = blockIdx.x * blockDim.x + threadIdx.x;
    if (e < EE) {
        int s = ei[e];
        int d = ei[EE + e];
        int p = atomicAdd(&g_cur[d], 1);
        g_srcs[p] = s;
    }
}

// ---------------- gather aggregation (CSR, no atomics) ----------------
// layer 0: warp per node, 4 feats; lane = c(0..3) + 4*sub(0..7)
__global__ void k_gather4() {
    int w = (blockIdx.x * blockDim.x + threadIdx.x) >> 5;
    if (w >= NN) return;
    int lane = threadIdx.x & 31;
    int c = lane & 3, sub = lane >> 2;
    int beg = g_off[w], dg = g_deg[w];
    float acc = (sub == 0) ? g_x4[w * 4 + c] : 0.f;
    for (int j = beg + sub; j < beg + dg; j += 8) {
        int s = g_srcs[j];
        acc += g_x4[s * 4 + c];
    }
    acc += __shfl_down_sync(0xffffffffu, acc, 16);
    acc += __shfl_down_sync(0xffffffffu, acc, 8);
    acc += __shfl_down_sync(0xffffffffu, acc, 4);
    if (sub == 0) g_agg[w * 4 + c] = acc;
}

// layers 1..2: warp per node, 64 fp16 feats; lane = c(0..15) + 16*half
// each lane loads uint2 = 4 halves; row = 128B = 4 sectors, fully coalesced
__device__ __forceinline__ float4 h4_to_f4(uint2 v) {
    __half2 lo = *reinterpret_cast<__half2*>(&v.x);
    __half2 hi = *reinterpret_cast<__half2*>(&v.y);
    float2 a = __half22float2(lo);
    float2 b = __half22float2(hi);
    return make_float4(a.x, a.y, b.x, b.y);
}

__global__ void k_gather64() {
    int w = (blockIdx.x * blockDim.x + threadIdx.x) >> 5;
    if (w >= NN) return;
    int lane = threadIdx.x & 31;
    int c = lane & 15, half = lane >> 4;
    int beg = g_off[w], dg = g_deg[w];
    const uint2* __restrict__ rows = reinterpret_cast<const uint2*>(g_xh);  // 16 uint2 per row
    float4 acc = make_float4(0.f, 0.f, 0.f, 0.f);
    if (half == 0) acc = h4_to_f4(rows[w * 16 + c]);   // self term
    for (int j = beg + half; j < beg + dg; j += 2) {
        int s = g_srcs[j];
        float4 v = h4_to_f4(rows[s * 16 + c]);
        acc.x += v.x; acc.y += v.y; acc.z += v.z; acc.w += v.w;
    }
    acc.x += __shfl_down_sync(0xffffffffu, acc.x, 16);
    acc.y += __shfl_down_sync(0xffffffffu, acc.y, 16);
    acc.z += __shfl_down_sync(0xffffffffu, acc.z, 16);
    acc.w += __shfl_down_sync(0xffffffffu, acc.w, 16);
    if (half == 0) *reinterpret_cast<float4*>(&g_agg[w * 64 + c * 4]) = acc;
}

// ---------------- fused MLP (two matmuls + ReLU) + BN-stat partial reduce ----------------
// Tile: 64 nodes x 64 feats per block, 256 threads, 4x4 micro-tile (f32x2 over node pairs)
template <int KIN>
__global__ __launch_bounds__(256) void k_mlp(const float* __restrict__ W1,
                                             const float* __restrict__ b1,
                                             const float* __restrict__ W2,
                                             const float* __restrict__ b2) {
    __shared__ float sA[64][68];  // [k][m], padded to keep float4 alignment
    __shared__ float sW[64][64];  // [k][f]

    const float* __restrict__ W1p = (KIN == 4) ? g_w1p : W1;

    const int m0 = blockIdx.x * 64;
    const int tid = threadIdx.x;
    const int tx = tid & 15;   // feature group (4 feats)
    const int ty = tid >> 4;   // node group (4 nodes)

    // load A = agg (already includes self term), transposed into sA
    for (int e = tid; e < 64 * (KIN / 4); e += 256) {
        int m = e / (KIN / 4);
        int k0 = (e % (KIN / 4)) * 4;
        int n = m0 + m;
        float4 v = make_float4(0.f, 0.f, 0.f, 0.f);
        if (n < NN) v = *reinterpret_cast<const float4*>(&g_agg[n * KIN + k0]);
        sA[k0 + 0][m] = v.x;
        sA[k0 + 1][m] = v.y;
        sA[k0 + 2][m] = v.z;
        sA[k0 + 3][m] = v.w;
    }
    // load W1
    for (int e = tid; e < KIN * 16; e += 256) {
        int k = e >> 4, f0 = (e & 15) * 4;
        *reinterpret_cast<float4*>(&sW[k][f0]) =
            *reinterpret_cast<const float4*>(&W1p[k * 64 + f0]);
    }
    __syncthreads();

    // stage 1: acc = A @ W1    acc[f][p] : feature tx*4+f, node pair (ty*4+2p, ty*4+2p+1)
    u64 acc[4][2] = {{0ull, 0ull}, {0ull, 0ull}, {0ull, 0ull}, {0ull, 0ull}};
    #pragma unroll
    for (int k = 0; k < KIN; k++) {
        float4 av = *reinterpret_cast<float4*>(&sA[k][ty * 4]);
        u64 a01 = pk2(av.x, av.y), a23 = pk2(av.z, av.w);
        float4 wv = *reinterpret_cast<float4*>(&sW[k][tx * 4]);
        u64 w0 = pk2(wv.x, wv.x), w1 = pk2(wv.y, wv.y);
        u64 w2_ = pk2(wv.z, wv.z), w3 = pk2(wv.w, wv.w);
        acc[0][0] = fma2(a01, w0, acc[0][0]); acc[0][1] = fma2(a23, w0, acc[0][1]);
        acc[1][0] = fma2(a01, w1, acc[1][0]); acc[1][1] = fma2(a23, w1, acc[1][1]);
        acc[2][0] = fma2(a01, w2_, acc[2][0]); acc[2][1] = fma2(a23, w2_, acc[2][1]);
        acc[3][0] = fma2(a01, w3, acc[3][0]); acc[3][1] = fma2(a23, w3, acc[3][1]);
    }
    float4 b1v = *reinterpret_cast<const float4*>(&b1[tx * 4]);
    __syncthreads();  // stage-1 readers done before sA/sW overwrite

    // bias + ReLU, write transposed back into sA: sA[feat][node]
    {
        float bb[4] = {b1v.x, b1v.y, b1v.z, b1v.w};
        #pragma unroll
        for (int f = 0; f < 4; f++) {
            float2 v0 = upk(acc[f][0]);
            float2 v1 = upk(acc[f][1]);
            sA[tx * 4 + f][ty * 4 + 0] = fmaxf(v0.x + bb[f], 0.f);
            sA[tx * 4 + f][ty * 4 + 1] = fmaxf(v0.y + bb[f], 0.f);
            sA[tx * 4 + f][ty * 4 + 2] = fmaxf(v1.x + bb[f], 0.f);
            sA[tx * 4 + f][ty * 4 + 3] = fmaxf(v1.y + bb[f], 0.f);
        }
    }
    for (int e = tid; e < 1024; e += 256) {
        int k = e >> 4, f0 = (e & 15) * 4;
        *reinterpret_cast<float4*>(&sW[k][f0]) =
            *reinterpret_cast<const float4*>(&W2[k * 64 + f0]);
    }
    __syncthreads();

    // stage 2: acc = T @ W2
    #pragma unroll
    for (int f = 0; f < 4; f++) { acc[f][0] = 0ull; acc[f][1] = 0ull; }
    #pragma unroll 8
    for (int k = 0; k < 64; k++) {
        float4 av = *reinterpret_cast<float4*>(&sA[k][ty * 4]);
        u64 a01 = pk2(av.x, av.y), a23 = pk2(av.z, av.w);
        float4 wv = *reinterpret_cast<float4*>(&sW[k][tx * 4]);
        u64 w0 = pk2(wv.x, wv.x), w1 = pk2(wv.y, wv.y);
        u64 w2_ = pk2(wv.z, wv.z), w3 = pk2(wv.w, wv.w);
        acc[0][0] = fma2(a01, w0, acc[0][0]); acc[0][1] = fma2(a23, w0, acc[0][1]);
        acc[1][0] = fma2(a01, w1, acc[1][0]); acc[1][1] = fma2(a23, w1, acc[1][1]);
        acc[2][0] = fma2(a01, w2_, acc[2][0]); acc[2][1] = fma2(a23, w2_, acc[2][1]);
        acc[3][0] = fma2(a01, w3, acc[3][0]); acc[3][1] = fma2(a23, w3, acc[3][1]);
    }
    float4 b2v = *reinterpret_cast<const float4*>(&b2[tx * 4]);

    // unpack -> per-node float4 over this thread's 4 features
    float2 u0a = upk(acc[0][0]), u0b = upk(acc[0][1]);
    float2 u1a = upk(acc[1][0]), u1b = upk(acc[1][1]);
    float2 u2a = upk(acc[2][0]), u2b = upk(acc[2][1]);
    float2 u3a = upk(acc[3][0]), u3b = upk(acc[3][1]);
    float4 hv[4];
    hv[0] = make_float4(u0a.x + b2v.x, u1a.x + b2v.y, u2a.x + b2v.z, u3a.x + b2v.w);
    hv[1] = make_float4(u0a.y + b2v.x, u1a.y + b2v.y, u2a.y + b2v.z, u3a.y + b2v.w);
    hv[2] = make_float4(u0b.x + b2v.x, u1b.x + b2v.y, u2b.x + b2v.z, u3b.x + b2v.w);
    hv[3] = make_float4(u0b.y + b2v.x, u1b.y + b2v.y, u2b.y + b2v.z, u3b.y + b2v.w);

    // h store + BN stat partials (per-feature sums over this thread's 4 nodes)
    float s[4] = {0.f, 0.f, 0.f, 0.f};
    float ss[4] = {0.f, 0.f, 0.f, 0.f};
    #pragma unroll
    for (int i = 0; i < 4; i++) {
        int n = m0 + ty * 4 + i;
        if (n < NN) {
            *reinterpret_cast<float4*>(&g_h[n * 64 + tx * 4]) = hv[i];
            s[0] += hv[i].x; ss[0] += hv[i].x * hv[i].x;
            s[1] += hv[i].y; ss[1] += hv[i].y * hv[i].y;
            s[2] += hv[i].z; ss[2] += hv[i].z * hv[i].z;
            s[3] += hv[i].w; ss[3] += hv[i].w * hv[i].w;
        }
    }
    __syncthreads();  // stage-2 readers done before reuse as scratch

    // block-level BN stat reduce: sA holds sums, sW holds sumsqs ([feat][ty])
    #pragma unroll
    for (int j = 0; j < 4; j++) {
        sA[tx * 4 + j][ty] = s[j];
        sW[tx * 4 + j][ty] = ss[j];
    }
    __syncthreads();
    if (tid < 64) {
        float a = 0.f, b = 0.f;
        #pragma unroll
        for (int i = 0; i < 16; i++) {
            a += sA[tid][i];
            b += sW[tid][i];
        }
        atomicAdd(&g_stats[tid], a);
        atomicAdd(&g_stats[64 + tid], b);
    }
}

// ---------------- BN apply + ReLU -> fp16 store (optionally fused pool scatter) ----------------
template <bool POOL>
__global__ void k_bn(const float* __restrict__ gamma, const float* __restrict__ beta,
                     const int* __restrict__ batch) {
    int idx = blockIdx.x * blockDim.x + threadIdx.x;
    if (idx >= NN * 16) return;
    int n = idx >> 4;
    int f0 = (idx & 15) * 4;
    const float inv = 1.0f / (float)NN;

    float4 hv = *reinterpret_cast<const float4*>(&g_h[n * 64 + f0]);
    float4 o;
    {
        float mu = g_stats[f0 + 0] * inv;
        float var = g_stats[64 + f0 + 0] * inv - mu * mu;
        o.x = fmaxf((hv.x - mu) * rsqrtf(var + BN_EPS) * gamma[f0 + 0] + beta[f0 + 0], 0.f);
    }
    {
        float mu = g_stats[f0 + 1] * inv;
        float var = g_stats[64 + f0 + 1] * inv - mu * mu;
        o.y = fmaxf((hv.y - mu) * rsqrtf(var + BN_EPS) * gamma[f0 + 1] + beta[f0 + 1], 0.f);
    }
    {
        float mu = g_stats[f0 + 2] * inv;
        float var = g_stats[64 + f0 + 2] * inv - mu * mu;
        o.z = fmaxf((hv.z - mu) * rsqrtf(var + BN_EPS) * gamma[f0 + 2] + beta[f0 + 2], 0.f);
    }
    {
        float mu = g_stats[f0 + 3] * inv;
        float var = g_stats[64 + f0 + 3] * inv - mu * mu;
        o.w = fmaxf((hv.w - mu) * rsqrtf(var + BN_EPS) * gamma[f0 + 3] + beta[f0 + 3], 0.f);
    }
    // fp16 store (4 halves = 8B)
    uint2 pk;
    __half2 lo = __floats2half2_rn(o.x, o.y);
    __half2 hi = __floats2half2_rn(o.z, o.w);
    pk.x = *reinterpret_cast<unsigned*>(&lo);
    pk.y = *reinterpret_cast<unsigned*>(&hi);
    *reinterpret_cast<uint2*>(&g_xh[n * 64 + f0]) = pk;
    if (POOL) {
        int g = batch[n];
        red_add_v4(&g_pool[g * 64 + f0], o);   // fp32 values -> pool accuracy unchanged
    }
}

// ---------------- final projection ----------------
__global__ void k_out(const float* __restrict__ wout, const float* __restrict__ bout,
                      float* __restrict__ out) {
    __shared__ float mean[64];
    int g = blockIdx.x, f = threadIdx.x;
    float c = g_cnt[g];
    float sum = g_pool[g * 64 + f];
    mean[f] = (c > 0.f) ? sum / fmaxf(c, 1.f) : 0.f;
    __syncthreads();
    float acc = bout[f];
    #pragma unroll 8
    for (int k = 0; k < 64; k++) acc += mean[k] * wout[k * 64 + f];
    out[g * 64 + f] = acc;
}

// ---------------- launcher ----------------
extern "C" void kernel_launch(void* const* d_in, const int* in_sizes, int n_in,
                              void* d_out, int out_size) {
    const float* x     = (const float*)d_in[0];
    const int*   ei    = (const int*)d_in[1];
    const int*   batch = (const int*)d_in[2];
    const float* w1_0  = (const float*)d_in[3];
    const float* w1_r  = (const float*)d_in[4];
    const float* b1    = (const float*)d_in[5];
    const float* w2    = (const float*)d_in[6];
    const float* b2    = (const float*)d_in[7];
    const float* gamma = (const float*)d_in[8];
    const float* beta  = (const float*)d_in[9];
    const float* wout  = (const float*)d_in[10];
    const float* bout  = (const float*)d_in[11];
    float* out = (float*)d_out;

    const int TPB = 256;
    const int nodeBlocks  = (NN + TPB - 1) / TPB;        // 391
    const int mlpBlocks   = (NN + 63) / 64;              // 1563
    const int bnBlocks    = (NN * 16 + TPB - 1) / TPB;   // 6250
    const int edgeBlocks  = (EE + TPB - 1) / TPB;        // 12500
    const int warpBlocks  = (NN * 32 + TPB - 1) / TPB;   // 12500 (warp per node)

    // prep + CSR build
    k_zero_pool<<<(GG * 64 + TPB - 1) / TPB, TPB>>>();
    k_prep<<<nodeBlocks, TPB>>>(x, batch);
    k_w1pad<<<1, 256>>>(w1_0);
    k_zero_deg<<<nodeBlocks, TPB>>>();
    k_hist<<<edgeBlocks, TPB>>>(ei);
    k_scan_sum<<<NSB, 256>>>();
    k_scan_top<<<1, 32>>>();
    k_scan_out<<<NSB, 256>>>();
    k_scatter<<<edgeBlocks, TPB>>>(ei);

    // ---- layer 0 (KIN = 4, padded) ----
    k_zero_stats<<<1, 128>>>();
    k_gather4<<<warpBlocks, TPB>>>();
    k_mlp<4><<<mlpBlocks, TPB>>>(nullptr, b1 + 0, w2 + 0, b2 + 0);
    k_bn<false><<<bnBlocks, TPB>>>(gamma + 0, beta + 0, nullptr);

    // ---- layer 1 ----
    k_zero_stats<<<1, 128>>>();
    k_gather64<<<warpBlocks, TPB>>>();
    k_mlp<64><<<mlpBlocks, TPB>>>(w1_r, b1 + 64, w2 + 4096, b2 + 64);
    k_bn<false><<<bnBlocks, TPB>>>(gamma + 64, beta + 64, nullptr);

    // ---- layer 2 (fuse pool into BN apply) ----
    k_zero_stats<<<1, 128>>>();
    k_gather64<<<warpBlocks, TPB>>>();
    k_mlp<64><<<mlpBlocks, TPB>>>(w1_r + 4096, b1 + 128, w2 + 8192, b2 + 128);
    k_bn<true><<<bnBlocks, TPB>>>(gamma + 128, beta + 128, batch);

    // ---- output projection ----
    k_out<<<GG, 64>>>(wout, bout, out);
}

// round 5
// speedup vs baseline: 2.2748x; 1.0153x over previous
#include <cuda_runtime.h>
#include <cuda_fp16.h>

#define NN 100000
#define EE 3200000
#define GG 512
#define HH 64
#define BN_EPS 1e-5f
#define SCAN_BLK 1024
#define NSB ((NN + SCAN_BLK - 1) / SCAN_BLK)   // 98

typedef unsigned long long u64;

// ---------------- scratch (static __device__ — no allocation) ----------------
__device__ __align__(16) float g_x4[NN * 4];      // padded input features [N][4]
__device__ __align__(16) __half g_xh[NN * 64];    // current activations, fp16 [N][64]
__device__ __align__(16) float g_agg[NN * 64];    // x + sum_neighbors (MLP input, fp32)
__device__ __align__(16) float g_h[NN * 64];      // pre-BN MLP output
__device__ __align__(16) float g_w1p[4 * 64];     // W1 of layer 0 padded 3->4 rows
__device__ float g_stats[3 * 128];                // per-layer: [0:64) sum, [64:128) sumsq
__device__ __align__(16) float g_pool[GG * 64];   // graph feature sums
__device__ float g_cnt[GG];                       // graph node counts
// CSR
__device__ int g_deg[NN];
__device__ int g_off[NN];
__device__ int g_cur[NN];
__device__ int g_srcs[EE];
__device__ int g_bsum[NSB];

// vector RED (sm_90+): global float4 add, no return
__device__ __forceinline__ void red_add_v4(float* p, float4 v) {
    asm volatile("red.global.add.v4.f32 [%0], {%1,%2,%3,%4};"
                 :: "l"(p), "f"(v.x), "f"(v.y), "f"(v.z), "f"(v.w) : "memory");
}

// packed f32x2 helpers (Blackwell — ptxas never auto-generates these)
__device__ __forceinline__ u64 pk2(float lo, float hi) {
    u64 r; asm("mov.b64 %0, {%1,%2};" : "=l"(r) : "f"(lo), "f"(hi)); return r;
}
__device__ __forceinline__ u64 fma2(u64 a, u64 b, u64 c) {
    u64 d; asm("fma.rn.f32x2 %0, %1, %2, %3;" : "=l"(d) : "l"(a), "l"(b), "l"(c)); return d;
}
__device__ __forceinline__ u64 add2(u64 a, u64 b) {
    u64 d; asm("add.rn.f32x2 %0, %1, %2;" : "=l"(d) : "l"(a), "l"(b)); return d;
}
__device__ __forceinline__ float2 upk(u64 v) {
    float2 f; asm("mov.b64 {%0,%1}, %2;" : "=f"(f.x), "=f"(f.y) : "l"(v)); return f;
}
__device__ __forceinline__ u64 h2f2(unsigned h) {
    __half2 hh = *reinterpret_cast<__half2*>(&h);
    float2 f = __half22float2(hh);
    return pk2(f.x, f.y);
}

// ---------------- init (fused zeroing + W1 pad) ----------------
__global__ void k_init(const float* __restrict__ w1_0) {
    int i = blockIdx.x * blockDim.x + threadIdx.x;
    if (i < NN) g_deg[i] = 0;
    if (i < GG * 64) g_pool[i] = 0.f;
    if (i < GG) g_cnt[i] = 0.f;
    if (i < 3 * 128) g_stats[i] = 0.f;
    if (i < 256) {
        int k = i >> 6, f = i & 63;
        g_w1p[i] = (k < 3) ? w1_0[k * 64 + f] : 0.f;
    }
}

__global__ void k_prep(const float* __restrict__ x, const int* __restrict__ batch) {
    int n = blockIdx.x * blockDim.x + threadIdx.x;
    if (n < NN) {
        float4 v;
        v.x = x[n * 3 + 0];
        v.y = x[n * 3 + 1];
        v.z = x[n * 3 + 2];
        v.w = 0.f;
        reinterpret_cast<float4*>(g_x4)[n] = v;
        atomicAdd(&g_cnt[batch[n]], 1.0f);
    }
}

// ---------------- CSR build ----------------
__global__ void k_hist(const int* __restrict__ ei) {
    int e = blockIdx.x * blockDim.x + threadIdx.x;
    if (e < EE) atomicAdd(&g_deg[ei[EE + e]], 1);
}

__global__ void k_scan_sum() {  // NSB blocks x 256 threads; 4 elems/thread
    __shared__ int sh[256];
    int b = blockIdx.x, t = threadIdx.x;
    int base = b * SCAN_BLK + t * 4;
    int s = 0;
    #pragma unroll
    for (int i = 0; i < 4; i++) {
        int idx = base + i;
        if (idx < NN) s += g_deg[idx];
    }
    sh[t] = s;
    __syncthreads();
    for (int d = 128; d > 0; d >>= 1) {
        if (t < d) sh[t] += sh[t + d];
        __syncthreads();
    }
    if (t == 0) g_bsum[b] = sh[0];
}

__global__ void k_scan_top() {  // serial exclusive scan over 98 partials
    if (threadIdx.x == 0) {
        int run = 0;
        for (int i = 0; i < NSB; i++) { int v = g_bsum[i]; g_bsum[i] = run; run += v; }
    }
}

__global__ void k_scan_out() {  // NSB blocks x 256 threads
    __shared__ int sh[256];
    int b = blockIdx.x, t = threadIdx.x;
    int base = b * SCAN_BLK + t * 4;
    int loc[4];
    int s = 0;
    #pragma unroll
    for (int i = 0; i < 4; i++) {
        int idx = base + i;
        int v = (idx < NN) ? g_deg[idx] : 0;
        loc[i] = s; s += v;
    }
    sh[t] = s;
    __syncthreads();
    for (int d = 1; d < 256; d <<= 1) {
        int v = (t >= d) ? sh[t - d] : 0;
        __syncthreads();
        sh[t] += v;
        __syncthreads();
    }
    int excl = sh[t] - s + g_bsum[b];
    #pragma unroll
    for (int i = 0; i < 4; i++) {
        int idx = base + i;
        if (idx < NN) {
            int o = excl + loc[i];
            g_off[idx] = o;
            g_cur[idx] = o;
        }
    }
}

__global__ void k_scatter(const int* __restrict__ ei) {
    int e = blockIdx.x * blockDim.x + threadIdx.x;
    if (e < EE) {
        int s = ei[e];
        int d = ei[EE + e];
        int p = atomicAdd(&g_cur[d], 1);
        g_srcs[p] = s;
    }
}

// ---------------- gather aggregation (CSR, no atomics) ----------------
// layer 0: warp per node, 4 feats; lane = c(0..3) + 4*sub(0..7)
__global__ void k_gather4() {
    int w = (blockIdx.x * blockDim.x + threadIdx.x) >> 5;
    if (w >= NN) return;
    int lane = threadIdx.x & 31;
    int c = lane & 3, sub = lane >> 2;
    int beg = g_off[w], dg = g_deg[w];
    float acc = (sub == 0) ? g_x4[w * 4 + c] : 0.f;
    for (int j = beg + sub; j < beg + dg; j += 8) {
        int s = g_srcs[j];
        acc += g_x4[s * 4 + c];
    }
    acc += __shfl_down_sync(0xffffffffu, acc, 16);
    acc += __shfl_down_sync(0xffffffffu, acc, 8);
    acc += __shfl_down_sync(0xffffffffu, acc, 4);
    if (sub == 0) g_agg[w * 4 + c] = acc;
}

// layers 1..2: warp per node; lane = r(0..7) chunk + q(0..3) edge slot.
// Each lane loads uint4 = 8 halves; 8 lanes cover a 128B row; 4 edges/iter.
// Index prefetched one iteration ahead; fp32 accumulation in packed f32x2.
__global__ void k_gather64() {
    int w = (blockIdx.x * blockDim.x + threadIdx.x) >> 5;
    if (w >= NN) return;
    int lane = threadIdx.x & 31;
    int r = lane & 7;    // uint4 chunk within row
    int q = lane >> 3;   // edge slot
    int beg = g_off[w];
    int end = beg + g_deg[w];
    const uint4* __restrict__ rows = reinterpret_cast<const uint4*>(g_xh);  // 8 per row

    u64 a0 = 0ull, a1 = 0ull, a2 = 0ull, a3 = 0ull;   // 8 fp32 accumulators (packed)
    if (q == 0) {  // self term
        uint4 v = rows[w * 8 + r];
        a0 = h2f2(v.x); a1 = h2f2(v.y); a2 = h2f2(v.z); a3 = h2f2(v.w);
    }
    int iters = (end - beg + 3) >> 2;
    int j = beg + q;
    int s = (j < end) ? g_srcs[j] : -1;
    for (int it = 0; it < iters; it++) {
        int jn = j + 4;
        int sn = (jn < end) ? g_srcs[jn] : -1;
        if (s >= 0) {
            uint4 v = rows[s * 8 + r];
            a0 = add2(a0, h2f2(v.x));
            a1 = add2(a1, h2f2(v.y));
            a2 = add2(a2, h2f2(v.z));
            a3 = add2(a3, h2f2(v.w));
        }
        s = sn; j = jn;
    }
    // reduce across q groups (lane stride 8): offsets 16, 8
    a0 = add2(a0, __shfl_down_sync(0xffffffffu, a0, 16));
    a1 = add2(a1, __shfl_down_sync(0xffffffffu, a1, 16));
    a2 = add2(a2, __shfl_down_sync(0xffffffffu, a2, 16));
    a3 = add2(a3, __shfl_down_sync(0xffffffffu, a3, 16));
    a0 = add2(a0, __shfl_down_sync(0xffffffffu, a0, 8));
    a1 = add2(a1, __shfl_down_sync(0xffffffffu, a1, 8));
    a2 = add2(a2, __shfl_down_sync(0xffffffffu, a2, 8));
    a3 = add2(a3, __shfl_down_sync(0xffffffffu, a3, 8));
    if (q == 0) {
        float2 f0 = upk(a0), f1 = upk(a1), f2 = upk(a2), f3 = upk(a3);
        *reinterpret_cast<float4*>(&g_agg[w * 64 + r * 8]) =
            make_float4(f0.x, f0.y, f1.x, f1.y);
        *reinterpret_cast<float4*>(&g_agg[w * 64 + r * 8 + 4]) =
            make_float4(f2.x, f2.y, f3.x, f3.y);
    }
}

// ---------------- fused MLP (two matmuls + ReLU) + BN-stat partial reduce ----------------
// Tile: 64 nodes x 64 feats per block, 256 threads, 4x4 micro-tile (f32x2 over node pairs)
template <int KIN>
__global__ __launch_bounds__(256) void k_mlp(const float* __restrict__ W1,
                                             const float* __restrict__ b1,
                                             const float* __restrict__ W2,
                                             const float* __restrict__ b2,
                                             int si) {
    __shared__ float sA[64][68];  // [k][m], padded to keep float4 alignment
    __shared__ float sW[64][64];  // [k][f]

    const float* __restrict__ W1p = (KIN == 4) ? g_w1p : W1;

    const int m0 = blockIdx.x * 64;
    const int tid = threadIdx.x;
    const int tx = tid & 15;   // feature group (4 feats)
    const int ty = tid >> 4;   // node group (4 nodes)

    // load A = agg (already includes self term), transposed into sA
    for (int e = tid; e < 64 * (KIN / 4); e += 256) {
        int m = e / (KIN / 4);
        int k0 = (e % (KIN / 4)) * 4;
        int n = m0 + m;
        float4 v = make_float4(0.f, 0.f, 0.f, 0.f);
        if (n < NN) v = *reinterpret_cast<const float4*>(&g_agg[n * KIN + k0]);
        sA[k0 + 0][m] = v.x;
        sA[k0 + 1][m] = v.y;
        sA[k0 + 2][m] = v.z;
        sA[k0 + 3][m] = v.w;
    }
    // load W1
    for (int e = tid; e < KIN * 16; e += 256) {
        int k = e >> 4, f0 = (e & 15) * 4;
        *reinterpret_cast<float4*>(&sW[k][f0]) =
            *reinterpret_cast<const float4*>(&W1p[k * 64 + f0]);
    }
    __syncthreads();

    // stage 1: acc = A @ W1    acc[f][p] : feature tx*4+f, node pair (ty*4+2p, ty*4+2p+1)
    u64 acc[4][2] = {{0ull, 0ull}, {0ull, 0ull}, {0ull, 0ull}, {0ull, 0ull}};
    #pragma unroll
    for (int k = 0; k < KIN; k++) {
        float4 av = *reinterpret_cast<float4*>(&sA[k][ty * 4]);
        u64 a01 = pk2(av.x, av.y), a23 = pk2(av.z, av.w);
        float4 wv = *reinterpret_cast<float4*>(&sW[k][tx * 4]);
        u64 w0 = pk2(wv.x, wv.x), w1 = pk2(wv.y, wv.y);
        u64 w2_ = pk2(wv.z, wv.z), w3 = pk2(wv.w, wv.w);
        acc[0][0] = fma2(a01, w0, acc[0][0]); acc[0][1] = fma2(a23, w0, acc[0][1]);
        acc[1][0] = fma2(a01, w1, acc[1][0]); acc[1][1] = fma2(a23, w1, acc[1][1]);
        acc[2][0] = fma2(a01, w2_, acc[2][0]); acc[2][1] = fma2(a23, w2_, acc[2][1]);
        acc[3][0] = fma2(a01, w3, acc[3][0]); acc[3][1] = fma2(a23, w3, acc[3][1]);
    }
    float4 b1v = *reinterpret_cast<const float4*>(&b1[tx * 4]);
    __syncthreads();  // stage-1 readers done before sA/sW overwrite

    // bias + ReLU, write transposed back into sA: sA[feat][node]
    {
        float bb[4] = {b1v.x, b1v.y, b1v.z, b1v.w};
        #pragma unroll
        for (int f = 0; f < 4; f++) {
            float2 v0 = upk(acc[f][0]);
            float2 v1 = upk(acc[f][1]);
            sA[tx * 4 + f][ty * 4 + 0] = fmaxf(v0.x + bb[f], 0.f);
            sA[tx * 4 + f][ty * 4 + 1] = fmaxf(v0.y + bb[f], 0.f);
            sA[tx * 4 + f][ty * 4 + 2] = fmaxf(v1.x + bb[f], 0.f);
            sA[tx * 4 + f][ty * 4 + 3] = fmaxf(v1.y + bb[f], 0.f);
        }
    }
    for (int e = tid; e < 1024; e += 256) {
        int k = e >> 4, f0 = (e & 15) * 4;
        *reinterpret_cast<float4*>(&sW[k][f0]) =
            *reinterpret_cast<const float4*>(&W2[k * 64 + f0]);
    }
    __syncthreads();

    // stage 2: acc = T @ W2
    #pragma unroll
    for (int f = 0; f < 4; f++) { acc[f][0] = 0ull; acc[f][1] = 0ull; }
    #pragma unroll 8
    for (int k = 0; k < 64; k++) {
        float4 av = *reinterpret_cast<float4*>(&sA[k][ty * 4]);
        u64 a01 = pk2(av.x, av.y), a23 = pk2(av.z, av.w);
        float4 wv = *reinterpret_cast<float4*>(&sW[k][tx * 4]);
        u64 w0 = pk2(wv.x, wv.x), w1 = pk2(wv.y, wv.y);
        u64 w2_ = pk2(wv.z, wv.z), w3 = pk2(wv.w, wv.w);
        acc[0][0] = fma2(a01, w0, acc[0][0]); acc[0][1] = fma2(a23, w0, acc[0][1]);
        acc[1][0] = fma2(a01, w1, acc[1][0]); acc[1][1] = fma2(a23, w1, acc[1][1]);
        acc[2][0] = fma2(a01, w2_, acc[2][0]); acc[2][1] = fma2(a23, w2_, acc[2][1]);
        acc[3][0] = fma2(a01, w3, acc[3][0]); acc[3][1] = fma2(a23, w3, acc[3][1]);
    }
    float4 b2v = *reinterpret_cast<const float4*>(&b2[tx * 4]);

    // unpack -> per-node float4 over this thread's 4 features
    float2 u0a = upk(acc[0][0]), u0b = upk(acc[0][1]);
    float2 u1a = upk(acc[1][0]), u1b = upk(acc[1][1]);
    float2 u2a = upk(acc[2][0]), u2b = upk(acc[2][1]);
    float2 u3a = upk(acc[3][0]), u3b = upk(acc[3][1]);
    float4 hv[4];
    hv[0] = make_float4(u0a.x + b2v.x, u1a.x + b2v.y, u2a.x + b2v.z, u3a.x + b2v.w);
    hv[1] = make_float4(u0a.y + b2v.x, u1a.y + b2v.y, u2a.y + b2v.z, u3a.y + b2v.w);
    hv[2] = make_float4(u0b.x + b2v.x, u1b.x + b2v.y, u2b.x + b2v.z, u3b.x + b2v.w);
    hv[3] = make_float4(u0b.y + b2v.x, u1b.y + b2v.y, u2b.y + b2v.z, u3b.y + b2v.w);

    // h store + BN stat partials (per-feature sums over this thread's 4 nodes)
    float s[4] = {0.f, 0.f, 0.f, 0.f};
    float ss[4] = {0.f, 0.f, 0.f, 0.f};
    #pragma unroll
    for (int i = 0; i < 4; i++) {
        int n = m0 + ty * 4 + i;
        if (n < NN) {
            *reinterpret_cast<float4*>(&g_h[n * 64 + tx * 4]) = hv[i];
            s[0] += hv[i].x; ss[0] += hv[i].x * hv[i].x;
            s[1] += hv[i].y; ss[1] += hv[i].y * hv[i].y;
            s[2] += hv[i].z; ss[2] += hv[i].z * hv[i].z;
            s[3] += hv[i].w; ss[3] += hv[i].w * hv[i].w;
        }
    }
    __syncthreads();  // stage-2 readers done before reuse as scratch

    // block-level BN stat reduce: sA holds sums, sW holds sumsqs ([feat][ty])
    #pragma unroll
    for (int j = 0; j < 4; j++) {
        sA[tx * 4 + j][ty] = s[j];
        sW[tx * 4 + j][ty] = ss[j];
    }
    __syncthreads();
    if (tid < 64) {
        float a = 0.f, b = 0.f;
        #pragma unroll
        for (int i = 0; i < 16; i++) {
            a += sA[tid][i];
            b += sW[tid][i];
        }
        atomicAdd(&g_stats[si + tid], a);
        atomicAdd(&g_stats[si + 64 + tid], b);
    }
}

// ---------------- BN apply + ReLU -> fp16 store (optionally fused pool scatter) ----------------
template <bool POOL>
__global__ void k_bn(const float* __restrict__ gamma, const float* __restrict__ beta,
                     const int* __restrict__ batch, int si) {
    int idx = blockIdx.x * blockDim.x + threadIdx.x;
    if (idx >= NN * 16) return;
    int n = idx >> 4;
    int f0 = (idx & 15) * 4;
    const float inv = 1.0f / (float)NN;
    const float* st = g_stats + si;

    float4 hv = *reinterpret_cast<const float4*>(&g_h[n * 64 + f0]);
    float4 o;
    {
        float mu = st[f0 + 0] * inv;
        float var = st[64 + f0 + 0] * inv - mu * mu;
        o.x = fmaxf((hv.x - mu) * rsqrtf(var + BN_EPS) * gamma[f0 + 0] + beta[f0 + 0], 0.f);
    }
    {
        float mu = st[f0 + 1] * inv;
        float var = st[64 + f0 + 1] * inv - mu * mu;
        o.y = fmaxf((hv.y - mu) * rsqrtf(var + BN_EPS) * gamma[f0 + 1] + beta[f0 + 1], 0.f);
    }
    {
        float mu = st[f0 + 2] * inv;
        float var = st[64 + f0 + 2] * inv - mu * mu;
        o.z = fmaxf((hv.z - mu) * rsqrtf(var + BN_EPS) * gamma[f0 + 2] + beta[f0 + 2], 0.f);
    }
    {
        float mu = st[f0 + 3] * inv;
        float var = st[64 + f0 + 3] * inv - mu * mu;
        o.w = fmaxf((hv.w - mu) * rsqrtf(var + BN_EPS) * gamma[f0 + 3] + beta[f0 + 3], 0.f);
    }
    // fp16 store (4 halves = 8B)
    uint2 pk;
    __half2 lo = __floats2half2_rn(o.x, o.y);
    __half2 hi = __floats2half2_rn(o.z, o.w);
    pk.x = *reinterpret_cast<unsigned*>(&lo);
    pk.y = *reinterpret_cast<unsigned*>(&hi);
    *reinterpret_cast<uint2*>(&g_xh[n * 64 + f0]) = pk;
    if (POOL) {
        int g = batch[n];
        red_add_v4(&g_pool[g * 64 + f0], o);   // fp32 values -> pool accuracy unchanged
    }
}

// ---------------- final projection ----------------
__global__ void k_out(const float* __restrict__ wout, const float* __restrict__ bout,
                      float* __restrict__ out) {
    __shared__ float mean[64];
    int g = blockIdx.x, f = threadIdx.x;
    float c = g_cnt[g];
    float sum = g_pool[g * 64 + f];
    mean[f] = (c > 0.f) ? sum / fmaxf(c, 1.f) : 0.f;
    __syncthreads();
    float acc = bout[f];
    #pragma unroll 8
    for (int k = 0; k < 64; k++) acc += mean[k] * wout[k * 64 + f];
    out[g * 64 + f] = acc;
}

// ---------------- launcher ----------------
extern "C" void kernel_launch(void* const* d_in, const int* in_sizes, int n_in,
                              void* d_out, int out_size) {
    const float* x     = (const float*)d_in[0];
    const int*   ei    = (const int*)d_in[1];
    const int*   batch = (const int*)d_in[2];
    const float* w1_0  = (const float*)d_in[3];
    const float* w1_r  = (const float*)d_in[4];
    const float* b1    = (const float*)d_in[5];
    const float* w2    = (const float*)d_in[6];
    const float* b2    = (const float*)d_in[7];
    const float* gamma = (const float*)d_in[8];
    const float* beta  = (const float*)d_in[9];
    const float* wout  = (const float*)d_in[10];
    const float* bout  = (const float*)d_in[11];
    float* out = (float*)d_out;

    const int TPB = 256;
    const int nodeBlocks  = (NN + TPB - 1) / TPB;        // 391
    const int mlpBlocks   = (NN + 63) / 64;              // 1563
    const int bnBlocks    = (NN * 16 + TPB - 1) / TPB;   // 6250
    const int edgeBlocks  = (EE + TPB - 1) / TPB;        // 12500
    const int warpBlocks  = (NN * 32 + TPB - 1) / TPB;   // 12500 (warp per node)

    // init + CSR build
    k_init<<<nodeBlocks, TPB>>>(w1_0);
    k_prep<<<nodeBlocks, TPB>>>(x, batch);
    k_hist<<<edgeBlocks, TPB>>>(ei);
    k_scan_sum<<<NSB, 256>>>();
    k_scan_top<<<1, 32>>>();
    k_scan_out<<<NSB, 256>>>();
    k_scatter<<<edgeBlocks, TPB>>>(ei);

    // ---- layer 0 (KIN = 4, padded) ----
    k_gather4<<<warpBlocks, TPB>>>();
    k_mlp<4><<<mlpBlocks, TPB>>>(nullptr, b1 + 0, w2 + 0, b2 + 0, 0);
    k_bn<false><<<bnBlocks, TPB>>>(gamma + 0, beta + 0, nullptr, 0);

    // ---- layer 1 ----
    k_gather64<<<warpBlocks, TPB>>>();
    k_mlp<64><<<mlpBlocks, TPB>>>(w1_r, b1 + 64, w2 + 4096, b2 + 64, 128);
    k_bn<false><<<bnBlocks, TPB>>>(gamma + 64, beta + 64, nullptr, 128);

    // ---- layer 2 (fuse pool into BN apply) ----
    k_gather64<<<warpBlocks, TPB>>>();
    k_mlp<64><<<mlpBlocks, TPB>>>(w1_r + 4096, b1 + 128, w2 + 8192, b2 + 128, 256);
    k_bn<true><<<bnBlocks, TPB>>>(gamma + 128, beta + 128, batch, 256);

    // ---- output projection ----
    k_out<<<GG, 64>>>(wout, bout, out);
}

// round 6
// speedup vs baseline: 2.8694x; 1.2614x over previous
#include <cuda_runtime.h>
#include <cuda_fp16.h>

#define NN 100000
#define EE 3200000
#define GG 512
#define HH 64
#define BN_EPS 1e-5f
#define SCAN_BLK 1024
#define NSB ((NN + SCAN_BLK - 1) / SCAN_BLK)   // 98
#define WPITCH 88   // smem row pitch in halves: 176B = 16B-aligned, 12-bank shift/row

typedef unsigned long long u64;

// ---------------- scratch (static __device__ — no allocation) ----------------
__device__ __align__(16) float  g_x4[NN * 4];     // padded input features [N][4]
__device__ __align__(16) __half g_xh[NN * 64];    // post-BN activations, fp16 [N][64]
__device__ __align__(16) __half g_aggh[NN * 64];  // agg (self+neighbors), fp16; layer0 uses [N][16]
__device__ __align__(16) float  g_h[NN * 64];     // pre-BN MLP output (fp32)
__device__ __align__(16) __half g_w1ph[16 * 64];  // layer-0 W1 padded 3->16 rows, fp16
__device__ float g_stats[3 * 128];                // per-layer: [0:64) sum, [64:128) sumsq
__device__ __align__(16) float g_pool[GG * 64];   // graph feature sums
__device__ float g_cnt[GG];                       // graph node counts
// CSR
__device__ int g_deg[NN];
__device__ int g_off[NN];
__device__ int g_cur[NN];
__device__ int g_srcs[EE];
__device__ int g_bsum[NSB];

// vector RED (sm_90+): global float4 add, no return
__device__ __forceinline__ void red_add_v4(float* p, float4 v) {
    asm volatile("red.global.add.v4.f32 [%0], {%1,%2,%3,%4};"
                 :: "l"(p), "f"(v.x), "f"(v.y), "f"(v.z), "f"(v.w) : "memory");
}

// packed f32x2 helpers
__device__ __forceinline__ u64 pk2(float lo, float hi) {
    u64 r; asm("mov.b64 %0, {%1,%2};" : "=l"(r) : "f"(lo), "f"(hi)); return r;
}
__device__ __forceinline__ u64 add2(u64 a, u64 b) {
    u64 d; asm("add.rn.f32x2 %0, %1, %2;" : "=l"(d) : "l"(a), "l"(b)); return d;
}
__device__ __forceinline__ float2 upk(u64 v) {
    float2 f; asm("mov.b64 {%0,%1}, %2;" : "=f"(f.x), "=f"(f.y) : "l"(v)); return f;
}
__device__ __forceinline__ u64 h2f2(unsigned h) {
    __half2 hh = *reinterpret_cast<__half2*>(&h);
    float2 f = __half22float2(hh);
    return pk2(f.x, f.y);
}
__device__ __forceinline__ unsigned f22h2(float a, float b) {
    __half2 h = __floats2half2_rn(a, b);
    return *reinterpret_cast<unsigned*>(&h);
}

// ---------------- tensor-core primitives ----------------
__device__ __forceinline__ unsigned sptr(const void* p) {
    return (unsigned)__cvta_generic_to_shared(p);
}
__device__ __forceinline__ void ldsm_x4(unsigned* r, unsigned addr) {
    asm volatile("ldmatrix.sync.aligned.m8n8.x4.shared.b16 {%0,%1,%2,%3}, [%4];"
                 : "=r"(r[0]), "=r"(r[1]), "=r"(r[2]), "=r"(r[3]) : "r"(addr));
}
__device__ __forceinline__ void ldsm_x2t(unsigned* r, unsigned addr) {
    asm volatile("ldmatrix.sync.aligned.m8n8.x2.trans.shared.b16 {%0,%1}, [%2];"
                 : "=r"(r[0]), "=r"(r[1]) : "r"(addr));
}
__device__ __forceinline__ void mma16816(float* c, const unsigned* a, const unsigned* b) {
    asm volatile("mma.sync.aligned.m16n8k16.row.col.f32.f16.f16.f32 "
                 "{%0,%1,%2,%3}, {%4,%5,%6,%7}, {%8,%9}, {%0,%1,%2,%3};"
                 : "+f"(c[0]), "+f"(c[1]), "+f"(c[2]), "+f"(c[3])
                 : "r"(a[0]), "r"(a[1]), "r"(a[2]), "r"(a[3]), "r"(b[0]), "r"(b[1]));
}

// ---------------- init (fused zeroing + W1 pad + layer0 agg pad) ----------------
__global__ void k_init(const float* __restrict__ w1_0) {
    int i = blockIdx.x * blockDim.x + threadIdx.x;
    if (i < NN) {
        g_deg[i] = 0;
        // zero the [N][16] layer-0 agg region (cols 4..15 stay zero; gather4 fills 0..3)
        uint4 z = make_uint4(0, 0, 0, 0);
        *reinterpret_cast<uint4*>(&g_aggh[i * 16]) = z;
        *reinterpret_cast<uint4*>(&g_aggh[i * 16 + 8]) = z;
    }
    if (i < GG * 64) g_pool[i] = 0.f;
    if (i < GG) g_cnt[i] = 0.f;
    if (i < 3 * 128) g_stats[i] = 0.f;
    if (i < 16 * 64) {
        int k = i >> 6, f = i & 63;
        g_w1ph[i] = __float2half((k < 3) ? w1_0[k * 64 + f] : 0.f);
    }
}

__global__ void k_prep(const float* __restrict__ x, const int* __restrict__ batch) {
    int n = blockIdx.x * blockDim.x + threadIdx.x;
    if (n < NN) {
        float4 v;
        v.x = x[n * 3 + 0];
        v.y = x[n * 3 + 1];
        v.z = x[n * 3 + 2];
        v.w = 0.f;
        reinterpret_cast<float4*>(g_x4)[n] = v;
        atomicAdd(&g_cnt[batch[n]], 1.0f);
    }
}

// ---------------- CSR build ----------------
__global__ void k_hist(const int* __restrict__ ei) {
    int e = blockIdx.x * blockDim.x + threadIdx.x;
    if (e < EE) atomicAdd(&g_deg[ei[EE + e]], 1);
}

__global__ void k_scan_sum() {
    __shared__ int sh[256];
    int b = blockIdx.x, t = threadIdx.x;
    int base = b * SCAN_BLK + t * 4;
    int s = 0;
    #pragma unroll
    for (int i = 0; i < 4; i++) {
        int idx = base + i;
        if (idx < NN) s += g_deg[idx];
    }
    sh[t] = s;
    __syncthreads();
    for (int d = 128; d > 0; d >>= 1) {
        if (t < d) sh[t] += sh[t + d];
        __syncthreads();
    }
    if (t == 0) g_bsum[b] = sh[0];
}

__global__ void k_scan_top() {
    if (threadIdx.x == 0) {
        int run = 0;
        for (int i = 0; i < NSB; i++) { int v = g_bsum[i]; g_bsum[i] = run; run += v; }
    }
}

__global__ void k_scan_out() {
    __shared__ int sh[256];
    int b = blockIdx.x, t = threadIdx.x;
    int base = b * SCAN_BLK + t * 4;
    int loc[4];
    int s = 0;
    #pragma unroll
    for (int i = 0; i < 4; i++) {
        int idx = base + i;
        int v = (idx < NN) ? g_deg[idx] : 0;
        loc[i] = s; s += v;
    }
    sh[t] = s;
    __syncthreads();
    for (int d = 1; d < 256; d <<= 1) {
        int v = (t >= d) ? sh[t - d] : 0;
        __syncthreads();
        sh[t] += v;
        __syncthreads();
    }
    int excl = sh[t] - s + g_bsum[b];
    #pragma unroll
    for (int i = 0; i < 4; i++) {
        int idx = base + i;
        if (idx < NN) {
            int o = excl + loc[i];
            g_off[idx] = o;
            g_cur[idx] = o;
        }
    }
}

__global__ void k_scatter(const int* __restrict__ ei) {
    int e = blockIdx.x * blockDim.x + threadIdx.x;
    if (e < EE) {
        int s = ei[e];
        int d = ei[EE + e];
        int p = atomicAdd(&g_cur[d], 1);
        g_srcs[p] = s;
    }
}

// ---------------- gather aggregation (CSR, no atomics) ----------------
// layer 0: warp per node, 4 feats -> fp16 [N][16] (cols 4..15 pre-zeroed by k_init)
__global__ void k_gather4() {
    int w = (blockIdx.x * blockDim.x + threadIdx.x) >> 5;
    if (w >= NN) return;
    int lane = threadIdx.x & 31;
    int c = lane & 3, sub = lane >> 2;
    int beg = g_off[w], dg = g_deg[w];
    float acc = (sub == 0) ? g_x4[w * 4 + c] : 0.f;
    for (int j = beg + sub; j < beg + dg; j += 8) {
        int s = g_srcs[j];
        acc += g_x4[s * 4 + c];
    }
    acc += __shfl_down_sync(0xffffffffu, acc, 16);
    acc += __shfl_down_sync(0xffffffffu, acc, 8);
    acc += __shfl_down_sync(0xffffffffu, acc, 4);
    float v0 = __shfl_sync(0xffffffffu, acc, 0);
    float v1 = __shfl_sync(0xffffffffu, acc, 1);
    float v2 = __shfl_sync(0xffffffffu, acc, 2);
    float v3 = __shfl_sync(0xffffffffu, acc, 3);
    if (lane == 0) {
        uint2 o;
        o.x = f22h2(v0, v1);
        o.y = f22h2(v2, v3);
        *reinterpret_cast<uint2*>(&g_aggh[w * 16]) = o;
    }
}

// layers 1..2: warp per node; lane = r(0..7) chunk + q(0..3) edge slot; fp16 out
__global__ void k_gather64() {
    int w = (blockIdx.x * blockDim.x + threadIdx.x) >> 5;
    if (w >= NN) return;
    int lane = threadIdx.x & 31;
    int r = lane & 7;    // uint4 chunk within row
    int q = lane >> 3;   // edge slot
    int beg = g_off[w];
    int end = beg + g_deg[w];
    const uint4* __restrict__ rows = reinterpret_cast<const uint4*>(g_xh);  // 8 per row

    u64 a0 = 0ull, a1 = 0ull, a2 = 0ull, a3 = 0ull;
    if (q == 0) {  // self term
        uint4 v = rows[w * 8 + r];
        a0 = h2f2(v.x); a1 = h2f2(v.y); a2 = h2f2(v.z); a3 = h2f2(v.w);
    }
    int iters = (end - beg + 3) >> 2;
    int j = beg + q;
    int s = (j < end) ? g_srcs[j] : -1;
    for (int it = 0; it < iters; it++) {
        int jn = j + 4;
        int sn = (jn < end) ? g_srcs[jn] : -1;
        if (s >= 0) {
            uint4 v = rows[s * 8 + r];
            a0 = add2(a0, h2f2(v.x));
            a1 = add2(a1, h2f2(v.y));
            a2 = add2(a2, h2f2(v.z));
            a3 = add2(a3, h2f2(v.w));
        }
        s = sn; j = jn;
    }
    a0 = add2(a0, __shfl_down_sync(0xffffffffu, a0, 16));
    a1 = add2(a1, __shfl_down_sync(0xffffffffu, a1, 16));
    a2 = add2(a2, __shfl_down_sync(0xffffffffu, a2, 16));
    a3 = add2(a3, __shfl_down_sync(0xffffffffu, a3, 16));
    a0 = add2(a0, __shfl_down_sync(0xffffffffu, a0, 8));
    a1 = add2(a1, __shfl_down_sync(0xffffffffu, a1, 8));
    a2 = add2(a2, __shfl_down_sync(0xffffffffu, a2, 8));
    a3 = add2(a3, __shfl_down_sync(0xffffffffu, a3, 8));
    if (q == 0) {
        float2 f0 = upk(a0), f1 = upk(a1), f2 = upk(a2), f3 = upk(a3);
        uint4 o;
        o.x = f22h2(f0.x, f0.y);
        o.y = f22h2(f1.x, f1.y);
        o.z = f22h2(f2.x, f2.y);
        o.w = f22h2(f3.x, f3.y);
        *reinterpret_cast<uint4*>(&g_aggh[w * 64 + r * 8]) = o;
    }
}

// ---------------- HMMA MLP: h = relu(A @ W1 + b1) @ W2 + b2 ----------------
// 128 threads = 4 warps; block = 64 nodes; warp w owns rows 16w..16w+15.
// KS1 = stage-1 k-steps (1 for layer 0 [K=16 padded], 4 for layers 1..2 [K=64]).
template <int KS1>
__global__ __launch_bounds__(128) void k_mlp_hmma(const float* __restrict__ W1f,
                                                  const float* __restrict__ b1,
                                                  const float* __restrict__ W2f,
                                                  const float* __restrict__ b2) {
    __shared__ __half sA[64][WPITCH];
    __shared__ __half sW1[64][WPITCH];
    __shared__ __half sW2[64][WPITCH];

    const int tid = threadIdx.x;
    const int m0 = blockIdx.x * 64;

    // load A tile (fp16 agg)
    if (KS1 == 4) {
        for (int i = tid; i < 512; i += 128) {       // 64 rows x 8 uint4
            int r = i >> 3, c = i & 7;
            uint4 v = make_uint4(0, 0, 0, 0);
            if (m0 + r < NN) v = *reinterpret_cast<const uint4*>(&g_aggh[(m0 + r) * 64 + c * 8]);
            *reinterpret_cast<uint4*>(&sA[r][c * 8]) = v;
        }
    } else {
        for (int i = tid; i < 128; i += 128) {       // 64 rows x 2 uint4 (16 halves)
            int r = i >> 1, c = i & 1;
            uint4 v = make_uint4(0, 0, 0, 0);
            if (m0 + r < NN) v = *reinterpret_cast<const uint4*>(&g_aggh[(m0 + r) * 16 + c * 8]);
            *reinterpret_cast<uint4*>(&sA[r][c * 8]) = v;
        }
    }
    // load W1
    if (KS1 == 1) {
        for (int i = tid; i < 128; i += 128) {       // 16 rows x 8 uint4, already fp16
            int r = i >> 3, c = i & 7;
            *reinterpret_cast<uint4*>(&sW1[r][c * 8]) =
                *reinterpret_cast<const uint4*>(&g_w1ph[r * 64 + c * 8]);
        }
    } else {
        for (int i = tid; i < 1024; i += 128) {      // 64 rows x 16 float4-groups
            int r = i >> 4, c = i & 15;
            float4 v = *reinterpret_cast<const float4*>(&W1f[r * 64 + c * 4]);
            *reinterpret_cast<unsigned*>(&sW1[r][c * 4]) = f22h2(v.x, v.y);
            *reinterpret_cast<unsigned*>(&sW1[r][c * 4 + 2]) = f22h2(v.z, v.w);
        }
    }
    // load W2 (always 64x64 fp32)
    for (int i = tid; i < 1024; i += 128) {
        int r = i >> 4, c = i & 15;
        float4 v = *reinterpret_cast<const float4*>(&W2f[r * 64 + c * 4]);
        *reinterpret_cast<unsigned*>(&sW2[r][c * 4]) = f22h2(v.x, v.y);
        *reinterpret_cast<unsigned*>(&sW2[r][c * 4 + 2]) = f22h2(v.z, v.w);
    }
    __syncthreads();

    const int lane = tid & 31, w = tid >> 5;
    const int g = lane >> 2, tg = lane & 3;
    const int rowA = w * 16;

    // stage 1: C1[16x64] = A[16xK] @ W1[Kx64]
    float c1[8][4];
    #pragma unroll
    for (int j = 0; j < 8; j++)
        #pragma unroll
        for (int k = 0; k < 4; k++) c1[j][k] = 0.f;

    #pragma unroll
    for (int s = 0; s < KS1; s++) {
        unsigned a[4];
        ldsm_x4(a, sptr(&sA[rowA + (lane & 15)][s * 16 + (lane >> 4) * 8]));
        #pragma unroll
        for (int j = 0; j < 8; j++) {
            unsigned b[2];
            ldsm_x2t(b, sptr(&sW1[s * 16 + (lane & 15)][j * 8]));
            mma16816(c1[j], a, b);
        }
    }
    // bias + ReLU (C layout: rows g/g+8, cols j*8+tg*2+{0,1})
    #pragma unroll
    for (int j = 0; j < 8; j++) {
        float2 bb = *reinterpret_cast<const float2*>(&b1[j * 8 + tg * 2]);
        c1[j][0] = fmaxf(c1[j][0] + bb.x, 0.f);
        c1[j][1] = fmaxf(c1[j][1] + bb.y, 0.f);
        c1[j][2] = fmaxf(c1[j][2] + bb.x, 0.f);
        c1[j][3] = fmaxf(c1[j][3] + bb.y, 0.f);
    }

    // stage 2: C2[16x64] = T[16x64] @ W2[64x64]; A-frags built in-register from c1
    float c2[8][4];
    #pragma unroll
    for (int j = 0; j < 8; j++)
        #pragma unroll
        for (int k = 0; k < 4; k++) c2[j][k] = 0.f;

    #pragma unroll
    for (int s = 0; s < 4; s++) {
        unsigned a2[4];
        a2[0] = f22h2(c1[2 * s][0], c1[2 * s][1]);
        a2[1] = f22h2(c1[2 * s][2], c1[2 * s][3]);
        a2[2] = f22h2(c1[2 * s + 1][0], c1[2 * s + 1][1]);
        a2[3] = f22h2(c1[2 * s + 1][2], c1[2 * s + 1][3]);
        #pragma unroll
        for (int j = 0; j < 8; j++) {
            unsigned b[2];
            ldsm_x2t(b, sptr(&sW2[s * 16 + (lane & 15)][j * 8]));
            mma16816(c2[j], a2, b);
        }
    }

    // epilogue: +b2, store h (fp32)
    int r0 = m0 + rowA + g;
    int r1 = r0 + 8;
    #pragma unroll
    for (int j = 0; j < 8; j++) {
        float2 bb = *reinterpret_cast<const float2*>(&b2[j * 8 + tg * 2]);
        int col = j * 8 + tg * 2;
        if (r0 < NN)
            *reinterpret_cast<float2*>(&g_h[r0 * 64 + col]) =
                make_float2(c2[j][0] + bb.x, c2[j][1] + bb.y);
        if (r1 < NN)
            *reinterpret_cast<float2*>(&g_h[r1 * 64 + col]) =
                make_float2(c2[j][2] + bb.x, c2[j][3] + bb.y);
    }
}

// ---------------- BN stats (sum / sumsq per feature) ----------------
__global__ __launch_bounds__(256) void k_stats(int si) {
    __shared__ float sS[64][17];
    __shared__ float sQ[64][17];
    int tid = threadIdx.x;
    int tx = tid & 15, ty = tid >> 4;
    float s[4] = {0.f, 0.f, 0.f, 0.f}, q[4] = {0.f, 0.f, 0.f, 0.f};
    for (int n = blockIdx.x * 16 + ty; n < NN; n += gridDim.x * 16) {
        float4 v = *reinterpret_cast<const float4*>(&g_h[n * 64 + tx * 4]);
        s[0] += v.x; q[0] += v.x * v.x;
        s[1] += v.y; q[1] += v.y * v.y;
        s[2] += v.z; q[2] += v.z * v.z;
        s[3] += v.w; q[3] += v.w * v.w;
    }
    #pragma unroll
    for (int k = 0; k < 4; k++) { sS[tx * 4 + k][ty] = s[k]; sQ[tx * 4 + k][ty] = q[k]; }
    __syncthreads();
    if (tid < 64) {
        float a = 0.f, b = 0.f;
        #pragma unroll
        for (int i = 0; i < 16; i++) { a += sS[tid][i]; b += sQ[tid][i]; }
        atomicAdd(&g_stats[si + tid], a);
        atomicAdd(&g_stats[si + 64 + tid], b);
    }
}

// ---------------- BN apply + ReLU -> fp16 store (optionally fused pool scatter) ----------------
template <bool POOL>
__global__ void k_bn(const float* __restrict__ gamma, const float* __restrict__ beta,
                     const int* __restrict__ batch, int si) {
    int idx = blockIdx.x * blockDim.x + threadIdx.x;
    if (idx >= NN * 16) return;
    int n = idx >> 4;
    int f0 = (idx & 15) * 4;
    const float inv = 1.0f / (float)NN;
    const float* st = g_stats + si;

    float4 hv = *reinterpret_cast<const float4*>(&g_h[n * 64 + f0]);
    float4 o;
    {
        float mu = st[f0 + 0] * inv;
        float var = st[64 + f0 + 0] * inv - mu * mu;
        o.x = fmaxf((hv.x - mu) * rsqrtf(var + BN_EPS) * gamma[f0 + 0] + beta[f0 + 0], 0.f);
    }
    {
        float mu = st[f0 + 1] * inv;
        float var = st[64 + f0 + 1] * inv - mu * mu;
        o.y = fmaxf((hv.y - mu) * rsqrtf(var + BN_EPS) * gamma[f0 + 1] + beta[f0 + 1], 0.f);
    }
    {
        float mu = st[f0 + 2] * inv;
        float var = st[64 + f0 + 2] * inv - mu * mu;
        o.z = fmaxf((hv.z - mu) * rsqrtf(var + BN_EPS) * gamma[f0 + 2] + beta[f0 + 2], 0.f);
    }
    {
        float mu = st[f0 + 3] * inv;
        float var = st[64 + f0 + 3] * inv - mu * mu;
        o.w = fmaxf((hv.w - mu) * rsqrtf(var + BN_EPS) * gamma[f0 + 3] + beta[f0 + 3], 0.f);
    }
    uint2 pk;
    pk.x = f22h2(o.x, o.y);
    pk.y = f22h2(o.z, o.w);
    *reinterpret_cast<uint2*>(&g_xh[n * 64 + f0]) = pk;
    if (POOL) {
        int g = batch[n];
        red_add_v4(&g_pool[g * 64 + f0], o);
    }
}

// ---------------- final projection ----------------
__global__ void k_out(const float* __restrict__ wout, const float* __restrict__ bout,
                      float* __restrict__ out) {
    __shared__ float mean[64];
    int g = blockIdx.x, f = threadIdx.x;
    float c = g_cnt[g];
    float sum = g_pool[g * 64 + f];
    mean[f] = (c > 0.f) ? sum / fmaxf(c, 1.f) : 0.f;
    __syncthreads();
    float acc = bout[f];
    #pragma unroll 8
    for (int k = 0; k < 64; k++) acc += mean[k] * wout[k * 64 + f];
    out[g * 64 + f] = acc;
}

// ---------------- launcher ----------------
extern "C" void kernel_launch(void* const* d_in, const int* in_sizes, int n_in,
                              void* d_out, int out_size) {
    const float* x     = (const float*)d_in[0];
    const int*   ei    = (const int*)d_in[1];
    const int*   batch = (const int*)d_in[2];
    const float* w1_0  = (const float*)d_in[3];
    const float* w1_r  = (const float*)d_in[4];
    const float* b1    = (const float*)d_in[5];
    const float* w2    = (const float*)d_in[6];
    const float* b2    = (const float*)d_in[7];
    const float* gamma = (const float*)d_in[8];
    const float* beta  = (const float*)d_in[9];
    const float* wout  = (const float*)d_in[10];
    const float* bout  = (const float*)d_in[11];
    float* out = (float*)d_out;

    const int TPB = 256;
    const int nodeBlocks  = (NN + TPB - 1) / TPB;        // 391
    const int mlpBlocks   = (NN + 63) / 64;              // 1563
    const int bnBlocks    = (NN * 16 + TPB - 1) / TPB;   // 6250
    const int edgeBlocks  = (EE + TPB - 1) / TPB;        // 12500
    const int warpBlocks  = (NN * 32 + TPB - 1) / TPB;   // 12500 (warp per node)
    const int statBlocks  = 625;

    // init + CSR build
    k_init<<<nodeBlocks, TPB>>>(w1_0);
    k_prep<<<nodeBlocks, TPB>>>(x, batch);
    k_hist<<<edgeBlocks, TPB>>>(ei);
    k_scan_sum<<<NSB, 256>>>();
    k_scan_top<<<1, 32>>>();
    k_scan_out<<<NSB, 256>>>();
    k_scatter<<<edgeBlocks, TPB>>>(ei);

    // ---- layer 0 (K padded 4->16) ----
    k_gather4<<<warpBlocks, TPB>>>();
    k_mlp_hmma<1><<<mlpBlocks, 128>>>(nullptr, b1 + 0, w2 + 0, b2 + 0);
    k_stats<<<statBlocks, 256>>>(0);
    k_bn<false><<<bnBlocks, TPB>>>(gamma + 0, beta + 0, nullptr, 0);

    // ---- layer 1 ----
    k_gather64<<<warpBlocks, TPB>>>();
    k_mlp_hmma<4><<<mlpBlocks, 128>>>(w1_r, b1 + 64, w2 + 4096, b2 + 64);
    k_stats<<<statBlocks, 256>>>(128);
    k_bn<false><<<bnBlocks, TPB>>>(gamma + 64, beta + 64, nullptr, 128);

    // ---- layer 2 (fuse pool into BN apply) ----
    k_gather64<<<warpBlocks, TPB>>>();
    k_mlp_hmma<4><<<mlpBlocks, 128>>>(w1_r + 4096, b1 + 128, w2 + 8192, b2 + 128);
    k_stats<<<statBlocks, 256>>>(256);
    k_bn<true><<<bnBlocks, TPB>>>(gamma + 128, beta + 128, batch, 256);

    // ---- output projection ----
    k_out<<<GG, 64>>>(wout, bout, out);
}

// round 8
// speedup vs baseline: 3.0585x; 1.0659x over previous
#include <cuda_runtime.h>
#include <cuda_fp16.h>

#define NN 100000
#define EE 3200000
#define GG 512
#define HH 64
#define BN_EPS 1e-5f
#define DCAP 128    // per-node neighbor bucket capacity (P(deg>128) < 1e-40 for Poisson(32))
#define WPITCH 88   // smem row pitch in halves: 176B = 16B-aligned, 12-bank shift/row

typedef unsigned long long u64;

// ---------------- scratch (static __device__ — no allocation) ----------------
__device__ __align__(16) float  g_x4[NN * 4];       // padded input features [N][4]
__device__ __align__(16) __half g_xh[NN * 64];      // post-BN activations, fp16 [N][64]
__device__ __align__(16) __half g_aggh[NN * 64];    // agg, fp16; layer0 uses [N][16]
__device__ __align__(16) float  g_h[NN * 64];       // pre-BN MLP output (fp32)
__device__ __align__(16) __half g_w1ph[16 * 64];    // layer-0 W1 padded 3->16 rows, fp16
__device__ float g_stats[3 * 128];                  // per-layer: [0:64) sum, [64:128) sumsq
__device__ __align__(16) float g_pool[GG * 64];     // graph feature sums
__device__ float g_cnt[GG];                         // graph node counts
// bucket CSR
__device__ int g_cur[NN];                           // per-node fill count (== degree)
__device__ int g_srcs[NN * DCAP];                   // neighbor lists, bucketed

// vector RED (sm_90+): global float4 add, no return
__device__ __forceinline__ void red_add_v4(float* p, float4 v) {
    asm volatile("red.global.add.v4.f32 [%0], {%1,%2,%3,%4};"
                 :: "l"(p), "f"(v.x), "f"(v.y), "f"(v.z), "f"(v.w) : "memory");
}

// packed f32x2 helpers
__device__ __forceinline__ u64 pk2(float lo, float hi) {
    u64 r; asm("mov.b64 %0, {%1,%2};" : "=l"(r) : "f"(lo), "f"(hi)); return r;
}
__device__ __forceinline__ u64 add2(u64 a, u64 b) {
    u64 d; asm("add.rn.f32x2 %0, %1, %2;" : "=l"(d) : "l"(a), "l"(b)); return d;
}
__device__ __forceinline__ float2 upk(u64 v) {
    float2 f; asm("mov.b64 {%0,%1}, %2;" : "=f"(f.x), "=f"(f.y) : "l"(v)); return f;
}
__device__ __forceinline__ u64 h2f2(unsigned h) {
    __half2 hh = *reinterpret_cast<__half2*>(&h);
    float2 f = __half22float2(hh);
    return pk2(f.x, f.y);
}
__device__ __forceinline__ unsigned f22h2(float a, float b) {
    __half2 h = __floats2half2_rn(a, b);
    return *reinterpret_cast<unsigned*>(&h);
}

// ---------------- tensor-core primitives ----------------
__device__ __forceinline__ unsigned sptr(const void* p) {
    return (unsigned)__cvta_generic_to_shared(p);
}
__device__ __forceinline__ void ldsm_x4(unsigned* r, unsigned addr) {
    asm volatile("ldmatrix.sync.aligned.m8n8.x4.shared.b16 {%0,%1,%2,%3}, [%4];"
                 : "=r"(r[0]), "=r"(r[1]), "=r"(r[2]), "=r"(r[3]) : "r"(addr));
}
__device__ __forceinline__ void ldsm_x2t(unsigned* r, unsigned addr) {
    asm volatile("ldmatrix.sync.aligned.m8n8.x2.trans.shared.b16 {%0,%1}, [%2];"
                 : "=r"(r[0]), "=r"(r[1]) : "r"(addr));
}
__device__ __forceinline__ void mma16816(float* c, const unsigned* a, const unsigned* b) {
    asm volatile("mma.sync.aligned.m16n8k16.row.col.f32.f16.f16.f32 "
                 "{%0,%1,%2,%3}, {%4,%5,%6,%7}, {%8,%9}, {%0,%1,%2,%3};"
                 : "+f"(c[0]), "+f"(c[1]), "+f"(c[2]), "+f"(c[3])
                 : "r"(a[0]), "r"(a[1]), "r"(a[2]), "r"(a[3]), "r"(b[0]), "r"(b[1]));
}

// ---------------- init: zero counters + pad W1 + zero layer0 agg tail ----------------
__global__ void k_init(const float* __restrict__ w1_0) {
    int i = blockIdx.x * blockDim.x + threadIdx.x;
    if (i < NN) {
        g_cur[i] = 0;
        uint4 z = make_uint4(0, 0, 0, 0);
        *reinterpret_cast<uint4*>(&g_aggh[i * 16]) = z;       // layer-0 cols 0..7
        *reinterpret_cast<uint4*>(&g_aggh[i * 16 + 8]) = z;   // layer-0 cols 8..15
    }
    if (i < GG * 64) g_pool[i] = 0.f;
    if (i < GG) g_cnt[i] = 0.f;
    if (i < 3 * 128) g_stats[i] = 0.f;
    if (i < 16 * 64) {
        int k = i >> 6, f = i & 63;
        g_w1ph[i] = __float2half((k < 3) ? w1_0[k * 64 + f] : 0.f);
    }
}

__global__ void k_prep(const float* __restrict__ x, const int* __restrict__ batch) {
    int n = blockIdx.x * blockDim.x + threadIdx.x;
    if (n < NN) {
        float4 v;
        v.x = x[n * 3 + 0];
        v.y = x[n * 3 + 1];
        v.z = x[n * 3 + 2];
        v.w = 0.f;
        reinterpret_cast<float4*>(g_x4)[n] = v;
        atomicAdd(&g_cnt[batch[n]], 1.0f);   // sorted batch -> REDUX aggregation
    }
}

// ---------------- one-pass bucket fill (replaces hist + scan + scatter) ----------------
__global__ void k_scatter(const int* __restrict__ ei) {
    int e = blockIdx.x * blockDim.x + threadIdx.x;
    if (e < EE) {
        int s = ei[e];
        int d = ei[EE + e];
        int p = atomicAdd(&g_cur[d], 1);
        if (p < DCAP) g_srcs[d * DCAP + p] = s;   // clamp: impossible-case safety
    }
}

// ---------------- gather aggregation (buckets, no atomics) ----------------
// layer 0: warp per node, 4 feats -> fp16 [N][16] (cols 4..15 pre-zeroed)
__global__ void k_gather4() {
    int w = (blockIdx.x * blockDim.x + threadIdx.x) >> 5;
    if (w >= NN) return;
    int lane = threadIdx.x & 31;
    int c = lane & 3, sub = lane >> 2;
    int beg = w * DCAP;
    int dg = min(g_cur[w], DCAP);
    float acc = (sub == 0) ? g_x4[w * 4 + c] : 0.f;
    for (int j = beg + sub; j < beg + dg; j += 8) {
        int s = g_srcs[j];
        acc += g_x4[s * 4 + c];
    }
    acc += __shfl_down_sync(0xffffffffu, acc, 16);
    acc += __shfl_down_sync(0xffffffffu, acc, 8);
    acc += __shfl_down_sync(0xffffffffu, acc, 4);
    float v0 = __shfl_sync(0xffffffffu, acc, 0);
    float v1 = __shfl_sync(0xffffffffu, acc, 1);
    float v2 = __shfl_sync(0xffffffffu, acc, 2);
    float v3 = __shfl_sync(0xffffffffu, acc, 3);
    if (lane == 0) {
        uint2 o;
        o.x = f22h2(v0, v1);
        o.y = f22h2(v2, v3);
        *reinterpret_cast<uint2*>(&g_aggh[w * 16]) = o;
    }
}

// layers 1..2: warp per node; lane = r(0..7) chunk + q(0..3) edge slot; fp16 out
__global__ void k_gather64() {
    int w = (blockIdx.x * blockDim.x + threadIdx.x) >> 5;
    if (w >= NN) return;
    int lane = threadIdx.x & 31;
    int r = lane & 7;    // uint4 chunk within row
    int q = lane >> 3;   // edge slot
    int beg = w * DCAP;
    int end = beg + min(g_cur[w], DCAP);
    const uint4* __restrict__ rows = reinterpret_cast<const uint4*>(g_xh);  // 8 per row

    u64 a0 = 0ull, a1 = 0ull, a2 = 0ull, a3 = 0ull;
    if (q == 0) {  // self term
        uint4 v = rows[w * 8 + r];
        a0 = h2f2(v.x); a1 = h2f2(v.y); a2 = h2f2(v.z); a3 = h2f2(v.w);
    }
    int iters = (end - beg - q + 3) >> 2;
    int j = beg + q;
    int s = (j < end) ? g_srcs[j] : -1;
    for (int it = 0; it < iters; it++) {
        int jn = j + 4;
        int sn = (jn < end) ? g_srcs[jn] : -1;
        if (s >= 0) {
            uint4 v = rows[s * 8 + r];
            a0 = add2(a0, h2f2(v.x));
            a1 = add2(a1, h2f2(v.y));
            a2 = add2(a2, h2f2(v.z));
            a3 = add2(a3, h2f2(v.w));
        }
        s = sn; j = jn;
    }
    a0 = add2(a0, __shfl_down_sync(0xffffffffu, a0, 16));
    a1 = add2(a1, __shfl_down_sync(0xffffffffu, a1, 16));
    a2 = add2(a2, __shfl_down_sync(0xffffffffu, a2, 16));
    a3 = add2(a3, __shfl_down_sync(0xffffffffu, a3, 16));
    a0 = add2(a0, __shfl_down_sync(0xffffffffu, a0, 8));
    a1 = add2(a1, __shfl_down_sync(0xffffffffu, a1, 8));
    a2 = add2(a2, __shfl_down_sync(0xffffffffu, a2, 8));
    a3 = add2(a3, __shfl_down_sync(0xffffffffu, a3, 8));
    if (q == 0) {
        float2 f0 = upk(a0), f1 = upk(a1), f2 = upk(a2), f3 = upk(a3);
        uint4 o;
        o.x = f22h2(f0.x, f0.y);
        o.y = f22h2(f1.x, f1.y);
        o.z = f22h2(f2.x, f2.y);
        o.w = f22h2(f3.x, f3.y);
        *reinterpret_cast<uint4*>(&g_aggh[w * 64 + r * 8]) = o;
    }
}

// ---------------- HMMA MLP + fused BN-stat reduce ----------------
// 128 threads = 4 warps; block = 64 nodes; warp w owns rows 16w..16w+15.
template <int KS1>
__global__ __launch_bounds__(128) void k_mlp_hmma(const float* __restrict__ W1f,
                                                  const float* __restrict__ b1,
                                                  const float* __restrict__ W2f,
                                                  const float* __restrict__ b2,
                                                  int si) {
    __shared__ __half sA[64][WPITCH];
    __shared__ __half sW1[64][WPITCH];
    __shared__ __half sW2[64][WPITCH];

    const int tid = threadIdx.x;
    const int m0 = blockIdx.x * 64;

    // load A tile (fp16 agg)
    if (KS1 == 4) {
        for (int i = tid; i < 512; i += 128) {       // 64 rows x 8 uint4
            int r = i >> 3, c = i & 7;
            uint4 v = make_uint4(0, 0, 0, 0);
            if (m0 + r < NN) v = *reinterpret_cast<const uint4*>(&g_aggh[(m0 + r) * 64 + c * 8]);
            *reinterpret_cast<uint4*>(&sA[r][c * 8]) = v;
        }
    } else {
        for (int i = tid; i < 128; i += 128) {       // 64 rows x 2 uint4 (16 halves)
            int r = i >> 1, c = i & 1;
            uint4 v = make_uint4(0, 0, 0, 0);
            if (m0 + r < NN) v = *reinterpret_cast<const uint4*>(&g_aggh[(m0 + r) * 16 + c * 8]);
            *reinterpret_cast<uint4*>(&sA[r][c * 8]) = v;
        }
    }
    // load W1
    if (KS1 == 1) {
        for (int i = tid; i < 128; i += 128) {       // 16 rows x 8 uint4, already fp16
            int r = i >> 3, c = i & 7;
            *reinterpret_cast<uint4*>(&sW1[r][c * 8]) =
                *reinterpret_cast<const uint4*>(&g_w1ph[r * 64 + c * 8]);
        }
    } else {
        for (int i = tid; i < 1024; i += 128) {
            int r = i >> 4, c = i & 15;
            float4 v = *reinterpret_cast<const float4*>(&W1f[r * 64 + c * 4]);
            *reinterpret_cast<unsigned*>(&sW1[r][c * 4]) = f22h2(v.x, v.y);
            *reinterpret_cast<unsigned*>(&sW1[r][c * 4 + 2]) = f22h2(v.z, v.w);
        }
    }
    // load W2 (64x64 fp32 -> fp16)
    for (int i = tid; i < 1024; i += 128) {
        int r = i >> 4, c = i & 15;
        float4 v = *reinterpret_cast<const float4*>(&W2f[r * 64 + c * 4]);
        *reinterpret_cast<unsigned*>(&sW2[r][c * 4]) = f22h2(v.x, v.y);
        *reinterpret_cast<unsigned*>(&sW2[r][c * 4 + 2]) = f22h2(v.z, v.w);
    }
    __syncthreads();

    const int lane = tid & 31, w = tid >> 5;
    const int g = lane >> 2, tg = lane & 3;
    const int rowA = w * 16;

    // stage 1: C1[16x64] = A[16xK] @ W1[Kx64]
    float c1[8][4];
    #pragma unroll
    for (int j = 0; j < 8; j++)
        #pragma unroll
        for (int k = 0; k < 4; k++) c1[j][k] = 0.f;

    #pragma unroll
    for (int s = 0; s < KS1; s++) {
        unsigned a[4];
        ldsm_x4(a, sptr(&sA[rowA + (lane & 15)][s * 16 + (lane >> 4) * 8]));
        #pragma unroll
        for (int j = 0; j < 8; j++) {
            unsigned b[2];
            ldsm_x2t(b, sptr(&sW1[s * 16 + (lane & 15)][j * 8]));
            mma16816(c1[j], a, b);
        }
    }
    // bias + ReLU (C layout: rows g/g+8, cols j*8+tg*2+{0,1})
    #pragma unroll
    for (int j = 0; j < 8; j++) {
        float2 bb = *reinterpret_cast<const float2*>(&b1[j * 8 + tg * 2]);
        c1[j][0] = fmaxf(c1[j][0] + bb.x, 0.f);
        c1[j][1] = fmaxf(c1[j][1] + bb.y, 0.f);
        c1[j][2] = fmaxf(c1[j][2] + bb.x, 0.f);
        c1[j][3] = fmaxf(c1[j][3] + bb.y, 0.f);
    }

    // stage 2: C2 = T @ W2; A-frags built in-register from c1
    float c2[8][4];
    #pragma unroll
    for (int j = 0; j < 8; j++)
        #pragma unroll
        for (int k = 0; k < 4; k++) c2[j][k] = 0.f;

    #pragma unroll
    for (int s = 0; s < 4; s++) {
        unsigned a2[4];
        a2[0] = f22h2(c1[2 * s][0], c1[2 * s][1]);
        a2[1] = f22h2(c1[2 * s][2], c1[2 * s][3]);
        a2[2] = f22h2(c1[2 * s + 1][0], c1[2 * s + 1][1]);
        a2[3] = f22h2(c1[2 * s + 1][2], c1[2 * s + 1][3]);
        #pragma unroll
        for (int j = 0; j < 8; j++) {
            unsigned b[2];
            ldsm_x2t(b, sptr(&sW2[s * 16 + (lane & 15)][j * 8]));
            mma16816(c2[j], a2, b);
        }
    }

    // epilogue: +b2, store h (fp32), accumulate per-column stat partials
    int r0 = m0 + rowA + g;
    int r1 = r0 + 8;
    bool v0 = (r0 < NN), v1 = (r1 < NN);
    float s2[8][2], q2[8][2];
    #pragma unroll
    for (int j = 0; j < 8; j++) {
        float2 bb = *reinterpret_cast<const float2*>(&b2[j * 8 + tg * 2]);
        int col = j * 8 + tg * 2;
        float h00 = c2[j][0] + bb.x, h01 = c2[j][1] + bb.y;
        float h10 = c2[j][2] + bb.x, h11 = c2[j][3] + bb.y;
        if (v0) *reinterpret_cast<float2*>(&g_h[r0 * 64 + col]) = make_float2(h00, h01);
        if (v1) *reinterpret_cast<float2*>(&g_h[r1 * 64 + col]) = make_float2(h10, h11);
        float a0 = v0 ? h00 : 0.f, a1 = v0 ? h01 : 0.f;
        float b0 = v1 ? h10 : 0.f, b1c = v1 ? h11 : 0.f;
        s2[j][0] = a0 + b0;
        s2[j][1] = a1 + b1c;
        q2[j][0] = a0 * a0 + b0 * b0;
        q2[j][1] = a1 * a1 + b1c * b1c;
    }
    // reduce over g (lanes stride 4, preserving tg)
    #pragma unroll
    for (int off = 16; off >= 4; off >>= 1) {
        #pragma unroll
        for (int j = 0; j < 8; j++) {
            s2[j][0] += __shfl_down_sync(0xffffffffu, s2[j][0], off);
            s2[j][1] += __shfl_down_sync(0xffffffffu, s2[j][1], off);
            q2[j][0] += __shfl_down_sync(0xffffffffu, q2[j][0], off);
            q2[j][1] += __shfl_down_sync(0xffffffffu, q2[j][1], off);
        }
    }
    __syncthreads();   // all warps done with sA/sW1/sW2 -> reuse as stat scratch
    float* sS = reinterpret_cast<float*>(sA);        // [64 cols][4 warps]
    float* sQ = sS + 256;
    if (g == 0) {
        #pragma unroll
        for (int j = 0; j < 8; j++) {
            int col = j * 8 + tg * 2;
            sS[col * 4 + w] = s2[j][0];
            sS[(col + 1) * 4 + w] = s2[j][1];
            sQ[col * 4 + w] = q2[j][0];
            sQ[(col + 1) * 4 + w] = q2[j][1];
        }
    }
    __syncthreads();
    if (tid < 64) {
        float a = sS[tid * 4] + sS[tid * 4 + 1] + sS[tid * 4 + 2] + sS[tid * 4 + 3];
        float b = sQ[tid * 4] + sQ[tid * 4 + 1] + sQ[tid * 4 + 2] + sQ[tid * 4 + 3];
        atomicAdd(&g_stats[si + tid], a);
        atomicAdd(&g_stats[si + 64 + tid], b);
    }
}

// ---------------- BN apply + ReLU -> fp16 store (optionally fused pool scatter) ----------------
template <bool POOL>
__global__ void k_bn(const float* __restrict__ gamma, const float* __restrict__ beta,
                     const int* __restrict__ batch, int si) {
    int idx = blockIdx.x * blockDim.x + threadIdx.x;
    if (idx >= NN * 16) return;
    int n = idx >> 4;
    int f0 = (idx & 15) * 4;
    const float inv = 1.0f / (float)NN;
    const float* st = g_stats + si;

    float4 hv = *reinterpret_cast<const float4*>(&g_h[n * 64 + f0]);
    float4 o;
    {
        float mu = st[f0 + 0] * inv;
        float var = st[64 + f0 + 0] * inv - mu * mu;
        o.x = fmaxf((hv.x - mu) * rsqrtf(var + BN_EPS) * gamma[f0 + 0] + beta[f0 + 0], 0.f);
    }
    {
        float mu = st[f0 + 1] * inv;
        float var = st[64 + f0 + 1] * inv - mu * mu;
        o.y = fmaxf((hv.y - mu) * rsqrtf(var + BN_EPS) * gamma[f0 + 1] + beta[f0 + 1], 0.f);
    }
    {
        float mu = st[f0 + 2] * inv;
        float var = st[64 + f0 + 2] * inv - mu * mu;
        o.z = fmaxf((hv.z - mu) * rsqrtf(var + BN_EPS) * gamma[f0 + 2] + beta[f0 + 2], 0.f);
    }
    {
        float mu = st[f0 + 3] * inv;
        float var = st[64 + f0 + 3] * inv - mu * mu;
        o.w = fmaxf((hv.w - mu) * rsqrtf(var + BN_EPS) * gamma[f0 + 3] + beta[f0 + 3], 0.f);
    }
    uint2 pk;
    pk.x = f22h2(o.x, o.y);
    pk.y = f22h2(o.z, o.w);
    *reinterpret_cast<uint2*>(&g_xh[n * 64 + f0]) = pk;
    if (POOL) {
        int g = batch[n];
        red_add_v4(&g_pool[g * 64 + f0], o);
    }
}

// ---------------- final projection ----------------
__global__ void k_out(const float* __restrict__ wout, const float* __restrict__ bout,
                      float* __restrict__ out) {
    __shared__ float mean[64];
    int g = blockIdx.x, f = threadIdx.x;
    float c = g_cnt[g];
    float sum = g_pool[g * 64 + f];
    mean[f] = (c > 0.f) ? sum / fmaxf(c, 1.f) : 0.f;
    __syncthreads();
    float acc = bout[f];
    #pragma unroll 8
    for (int k = 0; k < 64; k++) acc += mean[k] * wout[k * 64 + f];
    out[g * 64 + f] = acc;
}

// ---------------- launcher ----------------
extern "C" void kernel_launch(void* const* d_in, const int* in_sizes, int n_in,
                              void* d_out, int out_size) {
    const float* x     = (const float*)d_in[0];
    const int*   ei    = (const int*)d_in[1];
    const int*   batch = (const int*)d_in[2];
    const float* w1_0  = (const float*)d_in[3];
    const float* w1_r  = (const float*)d_in[4];
    const float* b1    = (const float*)d_in[5];
    const float* w2    = (const float*)d_in[6];
    const float* b2    = (const float*)d_in[7];
    const float* gamma = (const float*)d_in[8];
    const float* beta  = (const float*)d_in[9];
    const float* wout  = (const float*)d_in[10];
    const float* bout  = (const float*)d_in[11];
    float* out = (float*)d_out;

    const int TPB = 256;
    const int nodeBlocks  = (NN + TPB - 1) / TPB;        // 391
    const int mlpBlocks   = (NN + 63) / 64;              // 1563
    const int bnBlocks    = (NN * 16 + TPB - 1) / TPB;   // 6250
    const int edgeBlocks  = (EE + TPB - 1) / TPB;        // 12500
    const int warpBlocks  = (NN * 32 + TPB - 1) / TPB;   // 12500 (warp per node)

    // init + bucket fill
    k_init<<<nodeBlocks, TPB>>>(w1_0);
    k_prep<<<nodeBlocks, TPB>>>(x, batch);
    k_scatter<<<edgeBlocks, TPB>>>(ei);

    // ---- layer 0 (K padded 4->16) ----
    k_gather4<<<warpBlocks, TPB>>>();
    k_mlp_hmma<1><<<mlpBlocks, 128>>>(nullptr, b1 + 0, w2 + 0, b2 + 0, 0);
    k_bn<false><<<bnBlocks, TPB>>>(gamma + 0, beta + 0, nullptr, 0);

    // ---- layer 1 ----
    k_gather64<<<warpBlocks, TPB>>>();
    k_mlp_hmma<4><<<mlpBlocks, 128>>>(w1_r, b1 + 64, w2 + 4096, b2 + 64, 128);
    k_bn<false><<<bnBlocks, TPB>>>(gamma + 64, beta + 64, nullptr, 128);

    // ---- layer 2 (fuse pool into BN apply) ----
    k_gather64<<<warpBlocks, TPB>>>();
    k_mlp_hmma<4><<<mlpBlocks, 128>>>(w1_r + 4096, b1 + 128, w2 + 8192, b2 + 128, 256);
    k_bn<true><<<bnBlocks, TPB>>>(gamma + 128, beta + 128, batch, 256);

    // ---- output projection ----
    k_out<<<GG, 64>>>(wout, bout, out);
}